// round 1
// baseline (speedup 1.0000x reference)
#include <cuda_runtime.h>
#include <cuda_bf16.h>
#include <math.h>

// Problem constants
#define BB     8
#define NHID   256
#define LL     2048
#define NHEAD  8
#define HD     64
#define DD     512      // NHEAD*HD
#define DO     2048     // NHEAD*NHID
#define MM     (BB*LL)  // 16384

// Scratch (device globals: the sanctioned no-alloc scratch path)
__device__ float g_q[(size_t)MM * DD];
__device__ float g_k[(size_t)MM * DD];
__device__ float g_v[(size_t)MM * DD];
__device__ float g_att[(size_t)MM * DD];

// ---------------------------------------------------------------------------
// Kernel 1: QKV GEMM.  out[m][n] = sum_k xt[m][k] * W[k][n] + bias[n]
// xt[m][k] = x[b, k, l] with m = b*LL + l  (transpose read, coalesced in l)
// grid: (12, 128)  -> x: 3 weights * 4 n-tiles of 128, y: 128 m-tiles of 128
// ---------------------------------------------------------------------------
__global__ __launch_bounds__(256, 2)
void qkv_gemm(const float* __restrict__ x,
              const float* __restrict__ Wq, const float* __restrict__ bq,
              const float* __restrict__ Wk, const float* __restrict__ bk,
              const float* __restrict__ Wv, const float* __restrict__ bv)
{
    __shared__ float As[2][16][128];
    __shared__ float Bs[2][16][128];

    const int sel = blockIdx.x >> 2;
    const int n0  = (blockIdx.x & 3) * 128;
    const int m0  = blockIdx.y * 128;
    const float* W    = (sel == 0) ? Wq : (sel == 1) ? Wk : Wv;
    const float* bias = (sel == 0) ? bq : (sel == 1) ? bk : bv;
    float* out        = (sel == 0) ? g_q : (sel == 1) ? g_k : g_v;

    const int b  = m0 / LL;
    const int l0 = m0 % LL;
    const float* xb = x + (size_t)b * NHID * LL;

    const int tid = threadIdx.x;
    const int kk  = tid >> 5;        // 0..7
    const int mm  = (tid & 31) * 4;  // 0..124
    const int ty  = tid >> 4;        // 0..15
    const int tx  = tid & 15;        // 0..15

    float acc[8][8];
#pragma unroll
    for (int i = 0; i < 8; ++i)
#pragma unroll
        for (int j = 0; j < 8; ++j) acc[i][j] = 0.f;

    auto load_stage = [&](int kt, int buf) {
        const int k0 = kt * 16;
#pragma unroll
        for (int i = 0; i < 16; i += 8) {
            const int k = k0 + kk + i;
            float4 a = *reinterpret_cast<const float4*>(xb + (size_t)k * LL + l0 + mm);
            *reinterpret_cast<float4*>(&As[buf][kk + i][mm]) = a;
            float4 w = *reinterpret_cast<const float4*>(W + (size_t)k * DD + n0 + mm);
            *reinterpret_cast<float4*>(&Bs[buf][kk + i][mm]) = w;
        }
    };

    load_stage(0, 0);
    __syncthreads();

    const int KT = NHID / 16;  // 16
    for (int kt = 0; kt < KT; ++kt) {
        const int cur = kt & 1;
        if (kt + 1 < KT) load_stage(kt + 1, cur ^ 1);
#pragma unroll
        for (int k = 0; k < 16; ++k) {
            float a[8], w[8];
            *reinterpret_cast<float4*>(&a[0]) = *reinterpret_cast<float4*>(&As[cur][k][ty * 8]);
            *reinterpret_cast<float4*>(&a[4]) = *reinterpret_cast<float4*>(&As[cur][k][ty * 8 + 4]);
            *reinterpret_cast<float4*>(&w[0]) = *reinterpret_cast<float4*>(&Bs[cur][k][tx * 8]);
            *reinterpret_cast<float4*>(&w[4]) = *reinterpret_cast<float4*>(&Bs[cur][k][tx * 8 + 4]);
#pragma unroll
            for (int i = 0; i < 8; ++i)
#pragma unroll
                for (int j = 0; j < 8; ++j) acc[i][j] += a[i] * w[j];
        }
        __syncthreads();
    }

    float bv8[8];
#pragma unroll
    for (int j = 0; j < 8; ++j) bv8[j] = bias[n0 + tx * 8 + j];
#pragma unroll
    for (int i = 0; i < 8; ++i) {
        const int m = m0 + ty * 8 + i;
        float4 v0 = make_float4(acc[i][0] + bv8[0], acc[i][1] + bv8[1],
                                acc[i][2] + bv8[2], acc[i][3] + bv8[3]);
        float4 v1 = make_float4(acc[i][4] + bv8[4], acc[i][5] + bv8[5],
                                acc[i][6] + bv8[6], acc[i][7] + bv8[7]);
        *reinterpret_cast<float4*>(out + (size_t)m * DD + n0 + tx * 8)     = v0;
        *reinterpret_cast<float4*>(out + (size_t)m * DD + n0 + tx * 8 + 4) = v1;
    }
}

// ---------------------------------------------------------------------------
// Kernel 2: window-3 attention per (b, l, head).
// block = 256 threads = 2 rows; per row 128 threads: h = t/16, g = t%16,
// each thread owns 4 head-dims (float4). Zero-padded windows (matches the
// reference: padded positions contribute score 0, NOT -inf).
// ---------------------------------------------------------------------------
__global__ __launch_bounds__(256)
void attn_win3()
{
    const int tid = threadIdx.x;
    const int m   = blockIdx.x * 2 + (tid >> 7);
    const int t   = tid & 127;
    const int h   = t >> 4;
    const int g   = t & 15;
    const int l   = m & (LL - 1);

    const size_t base = (size_t)m * DD + h * HD + g * 4;
    const float4 q4 = *reinterpret_cast<const float4*>(g_q + base);

    float  s[3];
    float4 v4[3];
#pragma unroll
    for (int w = 0; w < 3; ++w) {
        const int lw = l + w - 1;
        float4 k4 = make_float4(0.f, 0.f, 0.f, 0.f);
        v4[w]     = make_float4(0.f, 0.f, 0.f, 0.f);
        if (lw >= 0 && lw < LL) {
            const float* kp = g_k + base + (w - 1) * DD;
            const float* vp = g_v + base + (w - 1) * DD;
            k4    = *reinterpret_cast<const float4*>(kp);
            v4[w] = *reinterpret_cast<const float4*>(vp);
        }
        float p = q4.x * k4.x + q4.y * k4.y + q4.z * k4.z + q4.w * k4.w;
        p += __shfl_xor_sync(0xffffffffu, p, 8);
        p += __shfl_xor_sync(0xffffffffu, p, 4);
        p += __shfl_xor_sync(0xffffffffu, p, 2);
        p += __shfl_xor_sync(0xffffffffu, p, 1);
        s[w] = p * 0.125f;  // 1/sqrt(64)
    }

    const float mx = fmaxf(s[0], fmaxf(s[1], s[2]));
    const float e0 = expf(s[0] - mx);
    const float e1 = expf(s[1] - mx);
    const float e2 = expf(s[2] - mx);
    const float inv = 1.f / (e0 + e1 + e2);

    float4 o;
    o.x = (e0 * v4[0].x + e1 * v4[1].x + e2 * v4[2].x) * inv;
    o.y = (e0 * v4[0].y + e1 * v4[1].y + e2 * v4[2].y) * inv;
    o.z = (e0 * v4[0].z + e1 * v4[1].z + e2 * v4[2].z) * inv;
    o.w = (e0 * v4[0].w + e1 * v4[1].w + e2 * v4[2].w) * inv;
    *reinterpret_cast<float4*>(g_att + base) = o;
}

// ---------------------------------------------------------------------------
// Kernel 3: WO GEMM with transposed store.
// out[b, n, l] = sum_k att[m][k] * Wo[k][n] + bo[n],  m = b*LL + l
// grid: (16, 128). Epilogue stages C through smem in 32-column chunks so the
// [n][l]-major global store is fully coalesced along l.
// ---------------------------------------------------------------------------
__global__ __launch_bounds__(256, 2)
void wo_gemm(const float* __restrict__ Wo, const float* __restrict__ bo,
             float* __restrict__ out)
{
    __shared__ float As[2][16][128];
    __shared__ float Bs[2][16][128];

    const int n0 = blockIdx.x * 128;
    const int m0 = blockIdx.y * 128;
    const int b  = m0 / LL;
    const int l0 = m0 % LL;

    const int tid = threadIdx.x;
    const int ty  = tid >> 4;
    const int tx  = tid & 15;
    const int ar  = tid >> 1;        // 0..127 (A row)
    const int ac  = (tid & 1) * 8;   // 0 or 8 (A k-subcol)
    const int kk  = tid >> 5;        // 0..7
    const int nn  = (tid & 31) * 4;  // 0..124

    float acc[8][8];
#pragma unroll
    for (int i = 0; i < 8; ++i)
#pragma unroll
        for (int j = 0; j < 8; ++j) acc[i][j] = 0.f;

    auto load_stage = [&](int kt, int buf) {
        const int k0 = kt * 16;
        // A: att rows are k-contiguous -> load along k, store transposed
        const float* ap = g_att + (size_t)(m0 + ar) * DD + k0 + ac;
        float4 a0 = *reinterpret_cast<const float4*>(ap);
        float4 a1 = *reinterpret_cast<const float4*>(ap + 4);
        As[buf][ac + 0][ar] = a0.x;  As[buf][ac + 1][ar] = a0.y;
        As[buf][ac + 2][ar] = a0.z;  As[buf][ac + 3][ar] = a0.w;
        As[buf][ac + 4][ar] = a1.x;  As[buf][ac + 5][ar] = a1.y;
        As[buf][ac + 6][ar] = a1.z;  As[buf][ac + 7][ar] = a1.w;
#pragma unroll
        for (int i = 0; i < 16; i += 8) {
            const int k = k0 + kk + i;
            float4 w = *reinterpret_cast<const float4*>(Wo + (size_t)k * DO + n0 + nn);
            *reinterpret_cast<float4*>(&Bs[buf][kk + i][nn]) = w;
        }
    };

    load_stage(0, 0);
    __syncthreads();

    const int KT = DD / 16;  // 32
    for (int kt = 0; kt < KT; ++kt) {
        const int cur = kt & 1;
        if (kt + 1 < KT) load_stage(kt + 1, cur ^ 1);
#pragma unroll
        for (int k = 0; k < 16; ++k) {
            float a[8], w[8];
            *reinterpret_cast<float4*>(&a[0]) = *reinterpret_cast<float4*>(&As[cur][k][ty * 8]);
            *reinterpret_cast<float4*>(&a[4]) = *reinterpret_cast<float4*>(&As[cur][k][ty * 8 + 4]);
            *reinterpret_cast<float4*>(&w[0]) = *reinterpret_cast<float4*>(&Bs[cur][k][tx * 8]);
            *reinterpret_cast<float4*>(&w[4]) = *reinterpret_cast<float4*>(&Bs[cur][k][tx * 8 + 4]);
#pragma unroll
            for (int i = 0; i < 8; ++i)
#pragma unroll
                for (int j = 0; j < 8; ++j) acc[i][j] += a[i] * w[j];
        }
        __syncthreads();
    }

    // Transposed epilogue: reuse As region (4096 floats) as Cs[32][128]
    float (*Cs)[128] = reinterpret_cast<float (*)[128]>(&As[0][0][0]);
    float* outb = out + (size_t)b * DO * LL;

#pragma unroll
    for (int c = 0; c < 4; ++c) {
        __syncthreads();
        if ((tx >> 2) == c) {
            const int txl = tx & 3;
#pragma unroll
            for (int j = 0; j < 8; ++j) {
                const int nl   = txl * 8 + j;               // 0..31 within chunk
                const float bv = bo[n0 + c * 32 + nl];
#pragma unroll
                for (int i = 0; i < 8; ++i)
                    Cs[nl][ty * 8 + i] = acc[i][j] + bv;
            }
        }
        __syncthreads();
        for (int t2 = tid; t2 < 32 * 32; t2 += 256) {
            const int row = t2 >> 5;
            const int col = (t2 & 31) * 4;
            float4 vv = *reinterpret_cast<float4*>(&Cs[row][col]);
            *reinterpret_cast<float4*>(outb + (size_t)(n0 + c * 32 + row) * LL + l0 + col) = vv;
        }
    }
}

// ---------------------------------------------------------------------------
extern "C" void kernel_launch(void* const* d_in, const int* in_sizes, int n_in,
                              void* d_out, int out_size)
{
    const float* x  = (const float*)d_in[0];
    const float* Wq = (const float*)d_in[1];
    const float* bq = (const float*)d_in[2];
    const float* Wk = (const float*)d_in[3];
    const float* bk = (const float*)d_in[4];
    const float* Wv = (const float*)d_in[5];
    const float* bv = (const float*)d_in[6];
    const float* Wo = (const float*)d_in[7];
    const float* bo = (const float*)d_in[8];
    float* out = (float*)d_out;

    dim3 g1(12, 128);
    qkv_gemm<<<g1, 256>>>(x, Wq, bq, Wk, bk, Wv, bv);

    attn_win3<<<MM / 2, 256>>>();

    dim3 g2(16, 128);
    wo_gemm<<<g2, 256>>>(Wo, bo, out);
}

// round 3
// speedup vs baseline: 2.5074x; 2.5074x over previous
#include <cuda_runtime.h>
#include <cuda_bf16.h>
#include <cstdint>
#include <math.h>

// ---------------------------------------------------------------------------
// Problem constants
// ---------------------------------------------------------------------------
#define BB     8
#define NHID   256
#define LL     2048
#define DD     512            // q/k/v channels
#define DOUT   2048
#define MM     (BB*LL)        // 16384
#define NQKV   1536           // q|k|v fused N
#define K1     768            // tripled K for QKV GEMM (3*256)
#define K2     1536           // tripled K for WO GEMM  (3*512)

// GEMM tiling (SM80-style, base-target mma.sync bf16)
#define BM     128
#define BN     256
#define BK     64
#define TH     256
#define STAGES 4
#define STAGE_A (BM*BK*2)          // 16 KB
#define STAGE_B (BN*BK*2)          // 32 KB
#define STAGE_SZ (STAGE_A+STAGE_B) // 48 KB
#define SMEM_SZ (STAGES*STAGE_SZ)  // 192 KB

// ---------------------------------------------------------------------------
// Scratch (device globals — sanctioned no-alloc path)
// ---------------------------------------------------------------------------
__device__ __nv_bfloat16 g_A1[(size_t)MM * K1];     // [m][ xhi | xlo | xhi ]
__device__ __nv_bfloat16 g_B1[(size_t)NQKV * K1];   // [n][ Whi | Whi | Wlo ]
__device__ __nv_bfloat16 g_A2[(size_t)MM * K2];     // [m][ atthi | attlo | atthi ]
__device__ __nv_bfloat16 g_B2[(size_t)DOUT * K2];   // [n][ Wohi | Wohi | Wolo ]
__device__ float         g_bias[NQKV];
__device__ float         g_qkv[(size_t)MM * NQKV];  // fp32 q|k|v

// ---------------------------------------------------------------------------
// Helpers (all base-target PTX: cp.async, ldmatrix, mma.sync)
// ---------------------------------------------------------------------------
__device__ __forceinline__ uint32_t smem_u32(const void* p) {
    uint32_t a;
    asm("{ .reg .u64 t; cvta.to.shared.u64 t, %1; cvt.u32.u64 %0, t; }"
        : "=r"(a) : "l"(p));
    return a;
}

#define SWZ(x) ((x) ^ ((((x) >> 7) & 7) << 4))   // Swizzle<3,4,3>, 128B rows

#define CPASYNC16(dst, src) \
    asm volatile("cp.async.cg.shared.global [%0], [%1], 16;" \
                 :: "r"(dst), "l"(src))
#define CPCOMMIT() asm volatile("cp.async.commit_group;" ::: "memory")
#define CPWAIT(n)  asm volatile("cp.async.wait_group %0;" :: "n"(n) : "memory")

__device__ __forceinline__ void ldsm4(uint32_t& r0, uint32_t& r1,
                                      uint32_t& r2, uint32_t& r3, uint32_t a) {
    asm volatile("ldmatrix.sync.aligned.m8n8.x4.shared.b16 {%0,%1,%2,%3}, [%4];"
                 : "=r"(r0), "=r"(r1), "=r"(r2), "=r"(r3) : "r"(a));
}

__device__ __forceinline__ void mma16816(float* d, const uint32_t* a,
                                         const uint32_t* b) {
    asm volatile(
        "mma.sync.aligned.m16n8k16.row.col.f32.bf16.bf16.f32 "
        "{%0,%1,%2,%3}, {%4,%5,%6,%7}, {%8,%9}, {%0,%1,%2,%3};"
        : "+f"(d[0]), "+f"(d[1]), "+f"(d[2]), "+f"(d[3])
        : "r"(a[0]), "r"(a[1]), "r"(a[2]), "r"(a[3]), "r"(b[0]), "r"(b[1]));
}

// ---------------------------------------------------------------------------
// Shared mainloop: acc += A[BMxK'] * B[BNxK']^T, both [row][k] bf16 k-major.
// 8 warps as 2(M)x4(N), warp tile 64x64, mma m16n8k16.
// ---------------------------------------------------------------------------
template <int KTOT>
__device__ __forceinline__ void gemm_mainloop(const __nv_bfloat16* __restrict__ Ag,
                                              const __nv_bfloat16* __restrict__ Bg,
                                              char* smem, float (&acc)[4][8][4])
{
    const int tid  = threadIdx.x;
    const int wid  = tid >> 5;
    const int lane = tid & 31;
    const int wm   = (wid & 1) * 64;
    const int wn   = (wid >> 1) * 64;
    const uint32_t sb = smem_u32(smem);
    const int KT = KTOT / BK;

    auto load_stage = [&](int kt, int s) {
        const uint32_t as = sb + s * STAGE_SZ;
        const uint32_t bs = as + STAGE_A;
        const __nv_bfloat16* Asrc = Ag + kt * BK;
        const __nv_bfloat16* Bsrc = Bg + kt * BK;
#pragma unroll
        for (int i = 0; i < 4; ++i) {           // A: 128 rows x 8 chunks
            const int idx = tid + i * TH;
            const int r = idx >> 3, c = idx & 7;
            CPASYNC16(as + SWZ(r * 128 + c * 16), Asrc + (size_t)r * KTOT + c * 8);
        }
#pragma unroll
        for (int i = 0; i < 8; ++i) {           // B: 256 rows x 8 chunks
            const int idx = tid + i * TH;
            const int r = idx >> 3, c = idx & 7;
            CPASYNC16(bs + SWZ(r * 128 + c * 16), Bsrc + (size_t)r * KTOT + c * 8);
        }
    };

    int fetch = 0;
    for (; fetch < STAGES - 1; ++fetch) { load_stage(fetch, fetch); CPCOMMIT(); }
    CPWAIT(STAGES - 2);
    __syncthreads();

    // per-thread ldmatrix address components (within-tile byte offsets)
    const int aRow = wm + (lane & 15);
    const int aCol = (lane >> 4) << 4;
    const int bRow = wn + ((lane >> 4) << 3) + (lane & 7);
    const int bCol = ((lane >> 3) & 1) << 4;

    for (int kt = 0; kt < KT; ++kt) {
        const uint32_t as = sb + (kt % STAGES) * STAGE_SZ;
        const uint32_t bs = as + STAGE_A;
#pragma unroll
        for (int ks = 0; ks < 4; ++ks) {
            uint32_t af[4][4], bf[4][4];
#pragma unroll
            for (int mi = 0; mi < 4; ++mi) {
                const uint32_t a = as + SWZ((aRow + mi * 16) * 128 + ks * 32 + aCol);
                ldsm4(af[mi][0], af[mi][1], af[mi][2], af[mi][3], a);
            }
#pragma unroll
            for (int ni = 0; ni < 4; ++ni) {
                const uint32_t a = bs + SWZ((bRow + ni * 16) * 128 + ks * 32 + bCol);
                ldsm4(bf[ni][0], bf[ni][1], bf[ni][2], bf[ni][3], a);
            }
#pragma unroll
            for (int mi = 0; mi < 4; ++mi)
#pragma unroll
                for (int ni = 0; ni < 4; ++ni) {
                    mma16816(acc[mi][ni * 2],     af[mi], &bf[ni][0]);
                    mma16816(acc[mi][ni * 2 + 1], af[mi], &bf[ni][2]);
                }
        }
        if (fetch < KT) { load_stage(fetch, fetch % STAGES); ++fetch; }
        CPCOMMIT();
        CPWAIT(STAGES - 2);
        __syncthreads();
    }
}

// ---------------------------------------------------------------------------
// QKV GEMM: g_qkv[m][n] = A1[m] . B1[n] + bias[n]   (fp32 out)
// ---------------------------------------------------------------------------
__global__ __launch_bounds__(TH, 1)
void qkv_gemm() {
    extern __shared__ __align__(1024) char smem[];
    const int n0 = blockIdx.x * BN;
    const int m0 = blockIdx.y * BM;

    float acc[4][8][4];
#pragma unroll
    for (int i = 0; i < 4; ++i)
#pragma unroll
        for (int j = 0; j < 8; ++j)
#pragma unroll
            for (int r = 0; r < 4; ++r) acc[i][j][r] = 0.f;

    gemm_mainloop<K1>(g_A1 + (size_t)m0 * K1, g_B1 + (size_t)n0 * K1, smem, acc);

    const int wid = threadIdx.x >> 5, lane = threadIdx.x & 31;
    const int wm = m0 + (wid & 1) * 64;
    const int wn = n0 + (wid >> 1) * 64;
#pragma unroll
    for (int mi = 0; mi < 4; ++mi) {
        const int r0 = wm + mi * 16 + (lane >> 2);
#pragma unroll
        for (int ni = 0; ni < 8; ++ni) {
            const int n = wn + ni * 8 + 2 * (lane & 3);
            const float b0 = g_bias[n], b1 = g_bias[n + 1];
            float2 v0 = make_float2(acc[mi][ni][0] + b0, acc[mi][ni][1] + b1);
            float2 v1 = make_float2(acc[mi][ni][2] + b0, acc[mi][ni][3] + b1);
            *reinterpret_cast<float2*>(&g_qkv[(size_t)r0 * NQKV + n])       = v0;
            *reinterpret_cast<float2*>(&g_qkv[(size_t)(r0 + 8) * NQKV + n]) = v1;
        }
    }
}

// ---------------------------------------------------------------------------
// WO GEMM: out[b][n][l] = A2[m] . B2[n] + bo[n], m = b*LL + l (transposed store)
// ---------------------------------------------------------------------------
#define CSTR 132
__global__ __launch_bounds__(TH, 1)
void wo_gemm(const float* __restrict__ bo, float* __restrict__ out) {
    extern __shared__ __align__(1024) char smem[];
    const int n0 = blockIdx.x * BN;
    const int m0 = blockIdx.y * BM;
    const int b  = m0 / LL;
    const int l0 = m0 % LL;

    float acc[4][8][4];
#pragma unroll
    for (int i = 0; i < 4; ++i)
#pragma unroll
        for (int j = 0; j < 8; ++j)
#pragma unroll
            for (int r = 0; r < 4; ++r) acc[i][j][r] = 0.f;

    gemm_mainloop<K2>(g_A2 + (size_t)m0 * K2, g_B2 + (size_t)n0 * K2, smem, acc);

    // Transpose through smem: Cs[n][m], n=256 rows, stride 132 floats
    float* Cs = reinterpret_cast<float*>(smem);
    const int wid = threadIdx.x >> 5, lane = threadIdx.x & 31;
    const int wm = (wid & 1) * 64;
    const int wn = (wid >> 1) * 64;
#pragma unroll
    for (int mi = 0; mi < 4; ++mi) {
        const int m = wm + mi * 16 + (lane >> 2);
#pragma unroll
        for (int ni = 0; ni < 8; ++ni) {
            const int n = wn + ni * 8 + 2 * (lane & 3);
            Cs[(size_t)n * CSTR + m]           = acc[mi][ni][0];
            Cs[(size_t)(n + 1) * CSTR + m]     = acc[mi][ni][1];
            Cs[(size_t)n * CSTR + m + 8]       = acc[mi][ni][2];
            Cs[(size_t)(n + 1) * CSTR + m + 8] = acc[mi][ni][3];
        }
    }
    __syncthreads();

    float* outb = out + (size_t)b * DOUT * LL;
    for (int i = threadIdx.x; i < BN * (BM / 4); i += TH) {
        const int n = i >> 5;          // 0..255
        const int c = (i & 31) * 4;    // 0..124
        const float bv = bo[n0 + n];
        float4 v;
        v.x = Cs[(size_t)n * CSTR + c + 0] + bv;
        v.y = Cs[(size_t)n * CSTR + c + 1] + bv;
        v.z = Cs[(size_t)n * CSTR + c + 2] + bv;
        v.w = Cs[(size_t)n * CSTR + c + 3] + bv;
        *reinterpret_cast<float4*>(outb + (size_t)(n0 + n) * LL + l0 + c) = v;
    }
}

// ---------------------------------------------------------------------------
// Conversions (fp32 -> bf16 hi/lo with transposes, K-tripled layouts)
// ---------------------------------------------------------------------------
__global__ __launch_bounds__(1024)
void conv_x_kernel(const float* __restrict__ x) {
    __shared__ float t[32][33];
    const int b  = blockIdx.z;
    const int c0 = blockIdx.y * 32, l0 = blockIdx.x * 32;
    const int tx = threadIdx.x, ty = threadIdx.y;
    t[ty][tx] = x[((size_t)(b * NHID + c0 + ty)) * LL + l0 + tx];
    __syncthreads();
    const float v = t[tx][ty];
    const __nv_bfloat16 hi = __float2bfloat16(v);
    const __nv_bfloat16 lo = __float2bfloat16(v - __bfloat162float(hi));
    const size_t o = (size_t)(b * LL + l0 + ty) * K1 + c0 + tx;
    g_A1[o]       = hi;   // Ahi
    g_A1[o + 256] = lo;   // Alo
    g_A1[o + 512] = hi;   // Ahi (dup)
}

__global__ __launch_bounds__(1024)
void conv_w_kernel(const float* __restrict__ W, __nv_bfloat16* __restrict__ dst,
                   int N, int roff, int dstride, int hi2off, int looff) {
    __shared__ float t[32][33];
    const int k0 = blockIdx.y * 32, n0 = blockIdx.x * 32;
    const int tx = threadIdx.x, ty = threadIdx.y;
    t[ty][tx] = W[(size_t)(k0 + ty) * N + n0 + tx];
    __syncthreads();
    const float v = t[tx][ty];
    const __nv_bfloat16 hi = __float2bfloat16(v);
    const __nv_bfloat16 lo = __float2bfloat16(v - __bfloat162float(hi));
    const size_t o = (size_t)(roff + n0 + ty) * dstride + k0 + tx;
    dst[o]          = hi;  // Bhi
    dst[o + hi2off] = hi;  // Bhi (dup)
    dst[o + looff]  = lo;  // Blo
}

__global__ void conv_bias_kernel(const float* __restrict__ bq,
                                 const float* __restrict__ bk,
                                 const float* __restrict__ bv) {
    const int i = blockIdx.x * 256 + threadIdx.x;
    if (i < DD)          g_bias[i] = bq[i];
    else if (i < 2 * DD) g_bias[i] = bk[i - DD];
    else if (i < NQKV)   g_bias[i] = bv[i - 2 * DD];
}

// ---------------------------------------------------------------------------
// Window-3 attention; emits att straight into the K-tripled A2 operand.
// ---------------------------------------------------------------------------
__global__ __launch_bounds__(256)
void attn_win3() {
    const int tid = threadIdx.x;
    const int m   = blockIdx.x * 2 + (tid >> 7);
    const int t   = tid & 127;
    const int h   = t >> 4;
    const int g   = t & 15;
    const int l   = m & (LL - 1);

    const size_t rowb = (size_t)m * NQKV;
    const int    co   = h * 64 + g * 4;
    const float4 q4 = *reinterpret_cast<const float4*>(g_qkv + rowb + co);

    float  s[3];
    float4 v4[3];
#pragma unroll
    for (int w = 0; w < 3; ++w) {
        const int lw = l + w - 1;
        float4 k4 = make_float4(0.f, 0.f, 0.f, 0.f);
        v4[w]     = make_float4(0.f, 0.f, 0.f, 0.f);
        if (lw >= 0 && lw < LL) {
            const size_t rb = rowb + (size_t)(w - 1) * NQKV;
            k4    = *reinterpret_cast<const float4*>(g_qkv + rb + DD + co);
            v4[w] = *reinterpret_cast<const float4*>(g_qkv + rb + 2 * DD + co);
        }
        float p = q4.x * k4.x + q4.y * k4.y + q4.z * k4.z + q4.w * k4.w;
        p += __shfl_xor_sync(0xffffffffu, p, 8);
        p += __shfl_xor_sync(0xffffffffu, p, 4);
        p += __shfl_xor_sync(0xffffffffu, p, 2);
        p += __shfl_xor_sync(0xffffffffu, p, 1);
        s[w] = p * 0.125f;   // 1/sqrt(64)
    }

    const float mx = fmaxf(s[0], fmaxf(s[1], s[2]));
    const float e0 = expf(s[0] - mx), e1 = expf(s[1] - mx), e2 = expf(s[2] - mx);
    const float inv = 1.f / (e0 + e1 + e2);

    float o[4];
    o[0] = (e0 * v4[0].x + e1 * v4[1].x + e2 * v4[2].x) * inv;
    o[1] = (e0 * v4[0].y + e1 * v4[1].y + e2 * v4[2].y) * inv;
    o[2] = (e0 * v4[0].z + e1 * v4[1].z + e2 * v4[2].z) * inv;
    o[3] = (e0 * v4[0].w + e1 * v4[1].w + e2 * v4[2].w) * inv;

    __nv_bfloat16 hi[4], lo[4];
#pragma unroll
    for (int i = 0; i < 4; ++i) {
        hi[i] = __float2bfloat16(o[i]);
        lo[i] = __float2bfloat16(o[i] - __bfloat162float(hi[i]));
    }
    const size_t ob = (size_t)m * K2 + co;
    *reinterpret_cast<uint2*>(g_A2 + ob)        = *reinterpret_cast<uint2*>(hi);
    *reinterpret_cast<uint2*>(g_A2 + ob + 512)  = *reinterpret_cast<uint2*>(lo);
    *reinterpret_cast<uint2*>(g_A2 + ob + 1024) = *reinterpret_cast<uint2*>(hi);
}

// ---------------------------------------------------------------------------
extern "C" void kernel_launch(void* const* d_in, const int* in_sizes, int n_in,
                              void* d_out, int out_size)
{
    const float* x  = (const float*)d_in[0];
    const float* Wq = (const float*)d_in[1];
    const float* bq = (const float*)d_in[2];
    const float* Wk = (const float*)d_in[3];
    const float* bk = (const float*)d_in[4];
    const float* Wv = (const float*)d_in[5];
    const float* bv = (const float*)d_in[6];
    const float* Wo = (const float*)d_in[7];
    const float* bo = (const float*)d_in[8];
    float* out = (float*)d_out;

    cudaFuncSetAttribute(qkv_gemm, cudaFuncAttributeMaxDynamicSharedMemorySize, SMEM_SZ);
    cudaFuncSetAttribute(wo_gemm,  cudaFuncAttributeMaxDynamicSharedMemorySize, SMEM_SZ);

    __nv_bfloat16 *b1, *b2;
    cudaGetSymbolAddress((void**)&b1, g_B1);
    cudaGetSymbolAddress((void**)&b2, g_B2);

    dim3 blk(32, 32);
    conv_x_kernel<<<dim3(LL / 32, NHID / 32, BB), blk>>>(x);
    conv_w_kernel<<<dim3(DD / 32, NHID / 32), blk>>>(Wq, b1, DD, 0,      K1, 256, 512);
    conv_w_kernel<<<dim3(DD / 32, NHID / 32), blk>>>(Wk, b1, DD, DD,     K1, 256, 512);
    conv_w_kernel<<<dim3(DD / 32, NHID / 32), blk>>>(Wv, b1, DD, 2 * DD, K1, 256, 512);
    conv_w_kernel<<<dim3(DOUT / 32, DD / 32), blk>>>(Wo, b2, DOUT, 0,    K2, 512, 1024);
    conv_bias_kernel<<<6, 256>>>(bq, bk, bv);

    qkv_gemm<<<dim3(NQKV / BN, MM / BM), TH, SMEM_SZ>>>();
    attn_win3<<<MM / 2, 256>>>();
    wo_gemm<<<dim3(DOUT / BN, MM / BM), TH, SMEM_SZ>>>(bo, out);
}

// round 4
// speedup vs baseline: 4.8350x; 1.9283x over previous
#include <cuda_runtime.h>
#include <cuda_fp16.h>
#include <cstdint>
#include <math.h>

// ---------------------------------------------------------------------------
// Problem constants
// ---------------------------------------------------------------------------
#define BB     8
#define NHID   256
#define LL     2048
#define DD     512            // q/k/v channels
#define DOUT   2048
#define MM     (BB*LL)        // 16384
#define NQKV   1536           // q|k|v fused N
#define K1     256            // QKV GEMM K (single-pass fp16)
#define K2     512            // WO GEMM K

// GEMM tiling (SM80-style, base-target mma.sync fp16)
#define BM     128
#define BN     256
#define BK     64
#define TH     256
#define STAGES 4
#define STAGE_A (BM*BK*2)          // 16 KB
#define STAGE_B (BN*BK*2)          // 32 KB
#define STAGE_SZ (STAGE_A+STAGE_B) // 48 KB
#define SMEM_SZ (STAGES*STAGE_SZ)  // 192 KB

// ---------------------------------------------------------------------------
// Scratch (device globals — sanctioned no-alloc path)
// ---------------------------------------------------------------------------
__device__ __half g_A1[(size_t)MM * K1];     // x^T  [m][k] fp16
__device__ __half g_B1[(size_t)NQKV * K1];   // [Wq|Wk|Wv]^T [n][k] fp16
__device__ __half g_A2[(size_t)MM * K2];     // att  [m][k] fp16
__device__ __half g_B2[(size_t)DOUT * K2];   // Wo^T [n][k] fp16
__device__ float  g_bias[NQKV];
__device__ float  g_qkv[(size_t)MM * NQKV];  // fp32 q|k|v

// ---------------------------------------------------------------------------
// Helpers (all base-target PTX: cp.async, ldmatrix, mma.sync)
// ---------------------------------------------------------------------------
__device__ __forceinline__ uint32_t smem_u32(const void* p) {
    uint32_t a;
    asm("{ .reg .u64 t; cvta.to.shared.u64 t, %1; cvt.u32.u64 %0, t; }"
        : "=r"(a) : "l"(p));
    return a;
}

#define SWZ(x) ((x) ^ ((((x) >> 7) & 7) << 4))   // Swizzle<3,4,3>, 128B rows

#define CPASYNC16(dst, src) \
    asm volatile("cp.async.cg.shared.global [%0], [%1], 16;" \
                 :: "r"(dst), "l"(src))
#define CPCOMMIT() asm volatile("cp.async.commit_group;" ::: "memory")
#define CPWAIT(n)  asm volatile("cp.async.wait_group %0;" :: "n"(n) : "memory")

__device__ __forceinline__ void ldsm4(uint32_t& r0, uint32_t& r1,
                                      uint32_t& r2, uint32_t& r3, uint32_t a) {
    asm volatile("ldmatrix.sync.aligned.m8n8.x4.shared.b16 {%0,%1,%2,%3}, [%4];"
                 : "=r"(r0), "=r"(r1), "=r"(r2), "=r"(r3) : "r"(a));
}

__device__ __forceinline__ void mma16816(float* d, const uint32_t* a,
                                         const uint32_t* b) {
    asm volatile(
        "mma.sync.aligned.m16n8k16.row.col.f32.f16.f16.f32 "
        "{%0,%1,%2,%3}, {%4,%5,%6,%7}, {%8,%9}, {%0,%1,%2,%3};"
        : "+f"(d[0]), "+f"(d[1]), "+f"(d[2]), "+f"(d[3])
        : "r"(a[0]), "r"(a[1]), "r"(a[2]), "r"(a[3]), "r"(b[0]), "r"(b[1]));
}

// ---------------------------------------------------------------------------
// Shared mainloop: acc += A[BMxK'] * B[BNxK']^T, both [row][k] fp16 k-major.
// 8 warps as 2(M)x4(N), warp tile 64x64, mma m16n8k16.
// ---------------------------------------------------------------------------
template <int KTOT>
__device__ __forceinline__ void gemm_mainloop(const __half* __restrict__ Ag,
                                              const __half* __restrict__ Bg,
                                              char* smem, float (&acc)[4][8][4])
{
    const int tid  = threadIdx.x;
    const int wid  = tid >> 5;
    const int lane = tid & 31;
    const int wm   = (wid & 1) * 64;
    const int wn   = (wid >> 1) * 64;
    const uint32_t sb = smem_u32(smem);
    const int KT = KTOT / BK;

    auto load_stage = [&](int kt, int s) {
        const uint32_t as = sb + s * STAGE_SZ;
        const uint32_t bs = as + STAGE_A;
        const __half* Asrc = Ag + kt * BK;
        const __half* Bsrc = Bg + kt * BK;
#pragma unroll
        for (int i = 0; i < 4; ++i) {           // A: 128 rows x 8 chunks
            const int idx = tid + i * TH;
            const int r = idx >> 3, c = idx & 7;
            CPASYNC16(as + SWZ(r * 128 + c * 16), Asrc + (size_t)r * KTOT + c * 8);
        }
#pragma unroll
        for (int i = 0; i < 8; ++i) {           // B: 256 rows x 8 chunks
            const int idx = tid + i * TH;
            const int r = idx >> 3, c = idx & 7;
            CPASYNC16(bs + SWZ(r * 128 + c * 16), Bsrc + (size_t)r * KTOT + c * 8);
        }
    };

    int fetch = 0;
    for (; fetch < STAGES - 1 && fetch < KT; ++fetch) { load_stage(fetch, fetch); CPCOMMIT(); }
    CPWAIT(STAGES - 2);
    __syncthreads();

    const int aRow = wm + (lane & 15);
    const int aCol = (lane >> 4) << 4;
    const int bRow = wn + ((lane >> 4) << 3) + (lane & 7);
    const int bCol = ((lane >> 3) & 1) << 4;

    for (int kt = 0; kt < KT; ++kt) {
        const uint32_t as = sb + (kt % STAGES) * STAGE_SZ;
        const uint32_t bs = as + STAGE_A;
#pragma unroll
        for (int ks = 0; ks < 4; ++ks) {
            uint32_t af[4][4], bf[4][4];
#pragma unroll
            for (int mi = 0; mi < 4; ++mi) {
                const uint32_t a = as + SWZ((aRow + mi * 16) * 128 + ks * 32 + aCol);
                ldsm4(af[mi][0], af[mi][1], af[mi][2], af[mi][3], a);
            }
#pragma unroll
            for (int ni = 0; ni < 4; ++ni) {
                const uint32_t a = bs + SWZ((bRow + ni * 16) * 128 + ks * 32 + bCol);
                ldsm4(bf[ni][0], bf[ni][1], bf[ni][2], bf[ni][3], a);
            }
#pragma unroll
            for (int mi = 0; mi < 4; ++mi)
#pragma unroll
                for (int ni = 0; ni < 4; ++ni) {
                    mma16816(acc[mi][ni * 2],     af[mi], &bf[ni][0]);
                    mma16816(acc[mi][ni * 2 + 1], af[mi], &bf[ni][2]);
                }
        }
        if (fetch < KT) { load_stage(fetch, fetch % STAGES); ++fetch; }
        CPCOMMIT();
        CPWAIT(STAGES - 2);
        __syncthreads();
    }
}

// ---------------------------------------------------------------------------
// QKV GEMM: g_qkv[m][n] = A1[m] . B1[n] + bias[n]   (fp32 out)
// ---------------------------------------------------------------------------
__global__ __launch_bounds__(TH, 1)
void qkv_gemm() {
    extern __shared__ __align__(1024) char smem[];
    const int n0 = blockIdx.x * BN;
    const int m0 = blockIdx.y * BM;

    float acc[4][8][4];
#pragma unroll
    for (int i = 0; i < 4; ++i)
#pragma unroll
        for (int j = 0; j < 8; ++j)
#pragma unroll
            for (int r = 0; r < 4; ++r) acc[i][j][r] = 0.f;

    gemm_mainloop<K1>(g_A1 + (size_t)m0 * K1, g_B1 + (size_t)n0 * K1, smem, acc);

    const int wid = threadIdx.x >> 5, lane = threadIdx.x & 31;
    const int wm = m0 + (wid & 1) * 64;
    const int wn = n0 + (wid >> 1) * 64;
#pragma unroll
    for (int mi = 0; mi < 4; ++mi) {
        const int r0 = wm + mi * 16 + (lane >> 2);
#pragma unroll
        for (int ni = 0; ni < 8; ++ni) {
            const int n = wn + ni * 8 + 2 * (lane & 3);
            const float b0 = g_bias[n], b1 = g_bias[n + 1];
            float2 v0 = make_float2(acc[mi][ni][0] + b0, acc[mi][ni][1] + b1);
            float2 v1 = make_float2(acc[mi][ni][2] + b0, acc[mi][ni][3] + b1);
            *reinterpret_cast<float2*>(&g_qkv[(size_t)r0 * NQKV + n])       = v0;
            *reinterpret_cast<float2*>(&g_qkv[(size_t)(r0 + 8) * NQKV + n]) = v1;
        }
    }
}

// ---------------------------------------------------------------------------
// WO GEMM: out[b][n][l] = A2[m] . B2[n] + bo[n], m = b*LL + l (transposed store)
// ---------------------------------------------------------------------------
#define CSTR 132
__global__ __launch_bounds__(TH, 1)
void wo_gemm(const float* __restrict__ bo, float* __restrict__ out) {
    extern __shared__ __align__(1024) char smem[];
    const int n0 = blockIdx.x * BN;
    const int m0 = blockIdx.y * BM;
    const int b  = m0 / LL;
    const int l0 = m0 % LL;

    float acc[4][8][4];
#pragma unroll
    for (int i = 0; i < 4; ++i)
#pragma unroll
        for (int j = 0; j < 8; ++j)
#pragma unroll
            for (int r = 0; r < 4; ++r) acc[i][j][r] = 0.f;

    gemm_mainloop<K2>(g_A2 + (size_t)m0 * K2, g_B2 + (size_t)n0 * K2, smem, acc);

    // Transpose through smem: Cs[n][m], n=256 rows, stride 132 floats
    float* Cs = reinterpret_cast<float*>(smem);
    const int wid = threadIdx.x >> 5, lane = threadIdx.x & 31;
    const int wm = (wid & 1) * 64;
    const int wn = (wid >> 1) * 64;
#pragma unroll
    for (int mi = 0; mi < 4; ++mi) {
        const int m = wm + mi * 16 + (lane >> 2);
#pragma unroll
        for (int ni = 0; ni < 8; ++ni) {
            const int n = wn + ni * 8 + 2 * (lane & 3);
            Cs[(size_t)n * CSTR + m]           = acc[mi][ni][0];
            Cs[(size_t)(n + 1) * CSTR + m]     = acc[mi][ni][1];
            Cs[(size_t)n * CSTR + m + 8]       = acc[mi][ni][2];
            Cs[(size_t)(n + 1) * CSTR + m + 8] = acc[mi][ni][3];
        }
    }
    __syncthreads();

    float* outb = out + (size_t)b * DOUT * LL;
    for (int i = threadIdx.x; i < BN * (BM / 4); i += TH) {
        const int n = i >> 5;          // 0..255
        const int c = (i & 31) * 4;    // 0..124
        const float bv = bo[n0 + n];
        float4 v;
        v.x = Cs[(size_t)n * CSTR + c + 0] + bv;
        v.y = Cs[(size_t)n * CSTR + c + 1] + bv;
        v.z = Cs[(size_t)n * CSTR + c + 2] + bv;
        v.w = Cs[(size_t)n * CSTR + c + 3] + bv;
        *reinterpret_cast<float4*>(outb + (size_t)(n0 + n) * LL + l0 + c) = v;
    }
}

// ---------------------------------------------------------------------------
// Conversions (fp32 -> fp16, with transposes)
// ---------------------------------------------------------------------------
__global__ __launch_bounds__(1024)
void conv_x_kernel(const float* __restrict__ x) {
    __shared__ float t[32][33];
    const int b  = blockIdx.z;
    const int c0 = blockIdx.y * 32, l0 = blockIdx.x * 32;
    const int tx = threadIdx.x, ty = threadIdx.y;
    t[ty][tx] = x[((size_t)(b * NHID + c0 + ty)) * LL + l0 + tx];
    __syncthreads();
    g_A1[(size_t)(b * LL + l0 + ty) * K1 + c0 + tx] = __float2half(t[tx][ty]);
}

__global__ __launch_bounds__(1024)
void conv_w_kernel(const float* __restrict__ W, __half* __restrict__ dst,
                   int N, int roff, int dstride) {
    __shared__ float t[32][33];
    const int k0 = blockIdx.y * 32, n0 = blockIdx.x * 32;
    const int tx = threadIdx.x, ty = threadIdx.y;
    t[ty][tx] = W[(size_t)(k0 + ty) * N + n0 + tx];
    __syncthreads();
    dst[(size_t)(roff + n0 + ty) * dstride + k0 + tx] = __float2half(t[tx][ty]);
}

__global__ void conv_bias_kernel(const float* __restrict__ bq,
                                 const float* __restrict__ bk,
                                 const float* __restrict__ bv) {
    const int i = blockIdx.x * 256 + threadIdx.x;
    if (i < DD)          g_bias[i] = bq[i];
    else if (i < 2 * DD) g_bias[i] = bk[i - DD];
    else if (i < NQKV)   g_bias[i] = bv[i - 2 * DD];
}

// ---------------------------------------------------------------------------
// Window-3 attention; emits att as fp16 A-operand for the WO GEMM.
// ---------------------------------------------------------------------------
__global__ __launch_bounds__(256)
void attn_win3() {
    const int tid = threadIdx.x;
    const int m   = blockIdx.x * 2 + (tid >> 7);
    const int t   = tid & 127;
    const int h   = t >> 4;
    const int g   = t & 15;
    const int l   = m & (LL - 1);

    const size_t rowb = (size_t)m * NQKV;
    const int    co   = h * 64 + g * 4;
    const float4 q4 = *reinterpret_cast<const float4*>(g_qkv + rowb + co);

    float  s[3];
    float4 v4[3];
#pragma unroll
    for (int w = 0; w < 3; ++w) {
        const int lw = l + w - 1;
        float4 k4 = make_float4(0.f, 0.f, 0.f, 0.f);
        v4[w]     = make_float4(0.f, 0.f, 0.f, 0.f);
        if (lw >= 0 && lw < LL) {
            const size_t rb = rowb + (size_t)(w - 1) * NQKV;
            k4    = *reinterpret_cast<const float4*>(g_qkv + rb + DD + co);
            v4[w] = *reinterpret_cast<const float4*>(g_qkv + rb + 2 * DD + co);
        }
        float p = q4.x * k4.x + q4.y * k4.y + q4.z * k4.z + q4.w * k4.w;
        p += __shfl_xor_sync(0xffffffffu, p, 8);
        p += __shfl_xor_sync(0xffffffffu, p, 4);
        p += __shfl_xor_sync(0xffffffffu, p, 2);
        p += __shfl_xor_sync(0xffffffffu, p, 1);
        s[w] = p * 0.125f;   // 1/sqrt(64)
    }

    const float mx = fmaxf(s[0], fmaxf(s[1], s[2]));
    const float e0 = expf(s[0] - mx), e1 = expf(s[1] - mx), e2 = expf(s[2] - mx);
    const float inv = 1.f / (e0 + e1 + e2);

    __half o[4];
    o[0] = __float2half((e0 * v4[0].x + e1 * v4[1].x + e2 * v4[2].x) * inv);
    o[1] = __float2half((e0 * v4[0].y + e1 * v4[1].y + e2 * v4[2].y) * inv);
    o[2] = __float2half((e0 * v4[0].z + e1 * v4[1].z + e2 * v4[2].z) * inv);
    o[3] = __float2half((e0 * v4[0].w + e1 * v4[1].w + e2 * v4[2].w) * inv);

    *reinterpret_cast<uint2*>(g_A2 + (size_t)m * K2 + co) = *reinterpret_cast<uint2*>(o);
}

// ---------------------------------------------------------------------------
extern "C" void kernel_launch(void* const* d_in, const int* in_sizes, int n_in,
                              void* d_out, int out_size)
{
    const float* x  = (const float*)d_in[0];
    const float* Wq = (const float*)d_in[1];
    const float* bq = (const float*)d_in[2];
    const float* Wk = (const float*)d_in[3];
    const float* bk = (const float*)d_in[4];
    const float* Wv = (const float*)d_in[5];
    const float* bv = (const float*)d_in[6];
    const float* Wo = (const float*)d_in[7];
    const float* bo = (const float*)d_in[8];
    float* out = (float*)d_out;

    cudaFuncSetAttribute(qkv_gemm, cudaFuncAttributeMaxDynamicSharedMemorySize, SMEM_SZ);
    cudaFuncSetAttribute(wo_gemm,  cudaFuncAttributeMaxDynamicSharedMemorySize, SMEM_SZ);

    __half *b1, *b2;
    cudaGetSymbolAddress((void**)&b1, g_B1);
    cudaGetSymbolAddress((void**)&b2, g_B2);

    dim3 blk(32, 32);
    conv_x_kernel<<<dim3(LL / 32, NHID / 32, BB), blk>>>(x);
    conv_w_kernel<<<dim3(DD / 32, NHID / 32), blk>>>(Wq, b1, DD, 0,      K1);
    conv_w_kernel<<<dim3(DD / 32, NHID / 32), blk>>>(Wk, b1, DD, DD,     K1);
    conv_w_kernel<<<dim3(DD / 32, NHID / 32), blk>>>(Wv, b1, DD, 2 * DD, K1);
    conv_w_kernel<<<dim3(DOUT / 32, DD / 32), blk>>>(Wo, b2, DOUT, 0,    K2);
    conv_bias_kernel<<<6, 256>>>(bq, bk, bv);

    qkv_gemm<<<dim3(NQKV / BN, MM / BM), TH, SMEM_SZ>>>();
    attn_win3<<<MM / 2, 256>>>();
    wo_gemm<<<dim3(DOUT / BN, MM / BM), TH, SMEM_SZ>>>(bo, out);
}

// round 5
// speedup vs baseline: 4.9485x; 1.0235x over previous
#include <cuda_runtime.h>
#include <cuda_fp16.h>
#include <cstdint>
#include <math.h>

// ---------------------------------------------------------------------------
// Problem constants
// ---------------------------------------------------------------------------
#define BB     8
#define NHID   256
#define LL     2048
#define DD     512            // q/k/v channels
#define DOUT   2048
#define MM     (BB*LL)        // 16384
#define NQKV   1536           // q|k|v fused N
#define K1     256            // QKV GEMM K (single-pass fp16)
#define K2     512            // WO GEMM K

// GEMM tiling (SM80-style, base-target mma.sync fp16)
#define BM     128
#define BN     256
#define BK     64
#define TH     256
#define STAGES 4
#define STAGE_A (BM*BK*2)          // 16 KB
#define STAGE_B (BN*BK*2)          // 32 KB
#define STAGE_SZ (STAGE_A+STAGE_B) // 48 KB
#define SMEM_SZ (STAGES*STAGE_SZ)  // 192 KB

// ---------------------------------------------------------------------------
// Scratch (device globals — sanctioned no-alloc path)
// ---------------------------------------------------------------------------
__device__ __half g_A1[(size_t)MM * K1];     // x^T  [m][k] fp16
__device__ __half g_B1[(size_t)NQKV * K1];   // [Wq|Wk|Wv]^T [n][k] fp16
__device__ __half g_A2[(size_t)MM * K2];     // att  [m][k] fp16
__device__ __half g_B2[(size_t)DOUT * K2];   // Wo^T [n][k] fp16
__device__ __half g_qkv[(size_t)MM * NQKV];  // fp16 q|k|v (bias included)

// ---------------------------------------------------------------------------
// Helpers (all base-target PTX: cp.async, ldmatrix, mma.sync)
// ---------------------------------------------------------------------------
__device__ __forceinline__ uint32_t smem_u32(const void* p) {
    uint32_t a;
    asm("{ .reg .u64 t; cvta.to.shared.u64 t, %1; cvt.u32.u64 %0, t; }"
        : "=r"(a) : "l"(p));
    return a;
}

#define SWZ(x) ((x) ^ ((((x) >> 7) & 7) << 4))   // Swizzle<3,4,3>, 128B rows

#define CPASYNC16(dst, src) \
    asm volatile("cp.async.cg.shared.global [%0], [%1], 16;" \
                 :: "r"(dst), "l"(src))
#define CPCOMMIT() asm volatile("cp.async.commit_group;" ::: "memory")
#define CPWAIT(n)  asm volatile("cp.async.wait_group %0;" :: "n"(n) : "memory")

__device__ __forceinline__ void ldsm4(uint32_t& r0, uint32_t& r1,
                                      uint32_t& r2, uint32_t& r3, uint32_t a) {
    asm volatile("ldmatrix.sync.aligned.m8n8.x4.shared.b16 {%0,%1,%2,%3}, [%4];"
                 : "=r"(r0), "=r"(r1), "=r"(r2), "=r"(r3) : "r"(a));
}

__device__ __forceinline__ void mma16816(float* d, const uint32_t* a,
                                         const uint32_t* b) {
    asm volatile(
        "mma.sync.aligned.m16n8k16.row.col.f32.f16.f16.f32 "
        "{%0,%1,%2,%3}, {%4,%5,%6,%7}, {%8,%9}, {%0,%1,%2,%3};"
        : "+f"(d[0]), "+f"(d[1]), "+f"(d[2]), "+f"(d[3])
        : "r"(a[0]), "r"(a[1]), "r"(a[2]), "r"(a[3]), "r"(b[0]), "r"(b[1]));
}

// ---------------------------------------------------------------------------
// Shared mainloop: acc += A[BMxK'] * B[BNxK']^T, both [row][k] fp16 k-major.
// 8 warps as 2(M)x4(N), warp tile 64x64, mma m16n8k16.
// ---------------------------------------------------------------------------
template <int KTOT>
__device__ __forceinline__ void gemm_mainloop(const __half* __restrict__ Ag,
                                              const __half* __restrict__ Bg,
                                              char* smem, float (&acc)[4][8][4])
{
    const int tid  = threadIdx.x;
    const int wid  = tid >> 5;
    const int lane = tid & 31;
    const int wm   = (wid & 1) * 64;
    const int wn   = (wid >> 1) * 64;
    const uint32_t sb = smem_u32(smem);
    const int KT = KTOT / BK;

    auto load_stage = [&](int kt, int s) {
        const uint32_t as = sb + s * STAGE_SZ;
        const uint32_t bs = as + STAGE_A;
        const __half* Asrc = Ag + kt * BK;
        const __half* Bsrc = Bg + kt * BK;
#pragma unroll
        for (int i = 0; i < 4; ++i) {           // A: 128 rows x 8 chunks
            const int idx = tid + i * TH;
            const int r = idx >> 3, c = idx & 7;
            CPASYNC16(as + SWZ(r * 128 + c * 16), Asrc + (size_t)r * KTOT + c * 8);
        }
#pragma unroll
        for (int i = 0; i < 8; ++i) {           // B: 256 rows x 8 chunks
            const int idx = tid + i * TH;
            const int r = idx >> 3, c = idx & 7;
            CPASYNC16(bs + SWZ(r * 128 + c * 16), Bsrc + (size_t)r * KTOT + c * 8);
        }
    };

    int fetch = 0;
    for (; fetch < STAGES - 1 && fetch < KT; ++fetch) { load_stage(fetch, fetch); CPCOMMIT(); }
    CPWAIT(STAGES - 2);
    __syncthreads();

    const int aRow = wm + (lane & 15);
    const int aCol = (lane >> 4) << 4;
    const int bRow = wn + ((lane >> 4) << 3) + (lane & 7);
    const int bCol = ((lane >> 3) & 1) << 4;

    for (int kt = 0; kt < KT; ++kt) {
        const uint32_t as = sb + (kt % STAGES) * STAGE_SZ;
        const uint32_t bs = as + STAGE_A;
#pragma unroll
        for (int ks = 0; ks < 4; ++ks) {
            uint32_t af[4][4], bf[4][4];
#pragma unroll
            for (int mi = 0; mi < 4; ++mi) {
                const uint32_t a = as + SWZ((aRow + mi * 16) * 128 + ks * 32 + aCol);
                ldsm4(af[mi][0], af[mi][1], af[mi][2], af[mi][3], a);
            }
#pragma unroll
            for (int ni = 0; ni < 4; ++ni) {
                const uint32_t a = bs + SWZ((bRow + ni * 16) * 128 + ks * 32 + bCol);
                ldsm4(bf[ni][0], bf[ni][1], bf[ni][2], bf[ni][3], a);
            }
#pragma unroll
            for (int mi = 0; mi < 4; ++mi)
#pragma unroll
                for (int ni = 0; ni < 4; ++ni) {
                    mma16816(acc[mi][ni * 2],     af[mi], &bf[ni][0]);
                    mma16816(acc[mi][ni * 2 + 1], af[mi], &bf[ni][2]);
                }
        }
        if (fetch < KT) { load_stage(fetch, fetch % STAGES); ++fetch; }
        CPCOMMIT();
        CPWAIT(STAGES - 2);
        __syncthreads();
    }
}

// ---------------------------------------------------------------------------
// QKV GEMM: g_qkv[m][n] = fp16( A1[m] . B1[n] + bias[n] )
// ---------------------------------------------------------------------------
__device__ __forceinline__ float qkv_bias(int n, const float* __restrict__ bq,
                                          const float* __restrict__ bk,
                                          const float* __restrict__ bv) {
    if (n < DD)     return bq[n];
    if (n < 2 * DD) return bk[n - DD];
    return bv[n - 2 * DD];
}

__global__ __launch_bounds__(TH, 1)
void qkv_gemm(const float* __restrict__ bq, const float* __restrict__ bk,
              const float* __restrict__ bv) {
    extern __shared__ __align__(1024) char smem[];
    const int n0 = blockIdx.x * BN;
    const int m0 = blockIdx.y * BM;

    float acc[4][8][4];
#pragma unroll
    for (int i = 0; i < 4; ++i)
#pragma unroll
        for (int j = 0; j < 8; ++j)
#pragma unroll
            for (int r = 0; r < 4; ++r) acc[i][j][r] = 0.f;

    gemm_mainloop<K1>(g_A1 + (size_t)m0 * K1, g_B1 + (size_t)n0 * K1, smem, acc);

    const int wid = threadIdx.x >> 5, lane = threadIdx.x & 31;
    const int wm = m0 + (wid & 1) * 64;
    const int wn = n0 + (wid >> 1) * 64;
#pragma unroll
    for (int mi = 0; mi < 4; ++mi) {
        const int r0 = wm + mi * 16 + (lane >> 2);
#pragma unroll
        for (int ni = 0; ni < 8; ++ni) {
            const int n = wn + ni * 8 + 2 * (lane & 3);
            const float b0 = qkv_bias(n, bq, bk, bv);
            const float b1 = qkv_bias(n + 1, bq, bk, bv);
            const __half2 v0 = __floats2half2_rn(acc[mi][ni][0] + b0, acc[mi][ni][1] + b1);
            const __half2 v1 = __floats2half2_rn(acc[mi][ni][2] + b0, acc[mi][ni][3] + b1);
            *reinterpret_cast<__half2*>(&g_qkv[(size_t)r0 * NQKV + n])       = v0;
            *reinterpret_cast<__half2*>(&g_qkv[(size_t)(r0 + 8) * NQKV + n]) = v1;
        }
    }
}

// ---------------------------------------------------------------------------
// WO GEMM: out[b][n][l] = A2[m] . B2[n] + bo[n], m = b*LL + l (transposed store)
// ---------------------------------------------------------------------------
#define CSTR 132
__global__ __launch_bounds__(TH, 1)
void wo_gemm(const float* __restrict__ bo, float* __restrict__ out) {
    extern __shared__ __align__(1024) char smem[];
    const int n0 = blockIdx.x * BN;
    const int m0 = blockIdx.y * BM;
    const int b  = m0 / LL;
    const int l0 = m0 % LL;

    float acc[4][8][4];
#pragma unroll
    for (int i = 0; i < 4; ++i)
#pragma unroll
        for (int j = 0; j < 8; ++j)
#pragma unroll
            for (int r = 0; r < 4; ++r) acc[i][j][r] = 0.f;

    gemm_mainloop<K2>(g_A2 + (size_t)m0 * K2, g_B2 + (size_t)n0 * K2, smem, acc);

    // Transpose through smem: Cs[n][m], n=256 rows, stride 132 floats
    float* Cs = reinterpret_cast<float*>(smem);
    const int wid = threadIdx.x >> 5, lane = threadIdx.x & 31;
    const int wm = (wid & 1) * 64;
    const int wn = (wid >> 1) * 64;
#pragma unroll
    for (int mi = 0; mi < 4; ++mi) {
        const int m = wm + mi * 16 + (lane >> 2);
#pragma unroll
        for (int ni = 0; ni < 8; ++ni) {
            const int n = wn + ni * 8 + 2 * (lane & 3);
            Cs[(size_t)n * CSTR + m]           = acc[mi][ni][0];
            Cs[(size_t)(n + 1) * CSTR + m]     = acc[mi][ni][1];
            Cs[(size_t)n * CSTR + m + 8]       = acc[mi][ni][2];
            Cs[(size_t)(n + 1) * CSTR + m + 8] = acc[mi][ni][3];
        }
    }
    __syncthreads();

    float* outb = out + (size_t)b * DOUT * LL;
    for (int i = threadIdx.x; i < BN * (BM / 4); i += TH) {
        const int n = i >> 5;          // 0..255
        const int c = (i & 31) * 4;    // 0..124
        const float bv = bo[n0 + n];
        float4 v;
        v.x = Cs[(size_t)n * CSTR + c + 0] + bv;
        v.y = Cs[(size_t)n * CSTR + c + 1] + bv;
        v.z = Cs[(size_t)n * CSTR + c + 2] + bv;
        v.w = Cs[(size_t)n * CSTR + c + 3] + bv;
        *reinterpret_cast<float4*>(outb + (size_t)(n0 + n) * LL + l0 + c) = v;
    }
}

// ---------------------------------------------------------------------------
// Conversions (fp32 -> fp16, with transposes)
// ---------------------------------------------------------------------------
__global__ __launch_bounds__(1024)
void conv_x_kernel(const float* __restrict__ x) {
    __shared__ float t[32][33];
    const int b  = blockIdx.z;
    const int c0 = blockIdx.y * 32, l0 = blockIdx.x * 32;
    const int tx = threadIdx.x, ty = threadIdx.y;
    t[ty][tx] = x[((size_t)(b * NHID + c0 + ty)) * LL + l0 + tx];
    __syncthreads();
    g_A1[(size_t)(b * LL + l0 + ty) * K1 + c0 + tx] = __float2half(t[tx][ty]);
}

__global__ __launch_bounds__(1024)
void conv_w_kernel(const float* __restrict__ W, __half* __restrict__ dst,
                   int N, int roff, int dstride) {
    __shared__ float t[32][33];
    const int k0 = blockIdx.y * 32, n0 = blockIdx.x * 32;
    const int tx = threadIdx.x, ty = threadIdx.y;
    t[ty][tx] = W[(size_t)(k0 + ty) * N + n0 + tx];
    __syncthreads();
    dst[(size_t)(roff + n0 + ty) * dstride + k0 + tx] = __float2half(t[tx][ty]);
}

// ---------------------------------------------------------------------------
// Window-3 attention (fp16 qkv in, fp16 att out)
// ---------------------------------------------------------------------------
__global__ __launch_bounds__(256)
void attn_win3() {
    const int tid = threadIdx.x;
    const int m   = blockIdx.x * 2 + (tid >> 7);
    const int t   = tid & 127;
    const int h   = t >> 4;
    const int g   = t & 15;
    const int l   = m & (LL - 1);

    const size_t rowb = (size_t)m * NQKV;
    const int    co   = h * 64 + g * 4;

    const uint2 qraw = *reinterpret_cast<const uint2*>(g_qkv + rowb + co);
    const float2 qa = __half22float2(*reinterpret_cast<const __half2*>(&qraw.x));
    const float2 qb = __half22float2(*reinterpret_cast<const __half2*>(&qraw.y));

    float  s[3];
    float2 va[3], vb[3];
#pragma unroll
    for (int w = 0; w < 3; ++w) {
        const int lw = l + w - 1;
        float2 ka = make_float2(0.f, 0.f), kb = make_float2(0.f, 0.f);
        va[w] = make_float2(0.f, 0.f);
        vb[w] = make_float2(0.f, 0.f);
        if (lw >= 0 && lw < LL) {
            const size_t rb = rowb + (size_t)(w - 1) * NQKV;
            const uint2 kr = *reinterpret_cast<const uint2*>(g_qkv + rb + DD + co);
            const uint2 vr = *reinterpret_cast<const uint2*>(g_qkv + rb + 2 * DD + co);
            ka = __half22float2(*reinterpret_cast<const __half2*>(&kr.x));
            kb = __half22float2(*reinterpret_cast<const __half2*>(&kr.y));
            va[w] = __half22float2(*reinterpret_cast<const __half2*>(&vr.x));
            vb[w] = __half22float2(*reinterpret_cast<const __half2*>(&vr.y));
        }
        float p = qa.x * ka.x + qa.y * ka.y + qb.x * kb.x + qb.y * kb.y;
        p += __shfl_xor_sync(0xffffffffu, p, 8);
        p += __shfl_xor_sync(0xffffffffu, p, 4);
        p += __shfl_xor_sync(0xffffffffu, p, 2);
        p += __shfl_xor_sync(0xffffffffu, p, 1);
        s[w] = p * 0.125f;   // 1/sqrt(64)
    }

    const float mx = fmaxf(s[0], fmaxf(s[1], s[2]));
    const float e0 = expf(s[0] - mx), e1 = expf(s[1] - mx), e2 = expf(s[2] - mx);
    const float inv = 1.f / (e0 + e1 + e2);

    __half o[4];
    o[0] = __float2half((e0 * va[0].x + e1 * va[1].x + e2 * va[2].x) * inv);
    o[1] = __float2half((e0 * va[0].y + e1 * va[1].y + e2 * va[2].y) * inv);
    o[2] = __float2half((e0 * vb[0].x + e1 * vb[1].x + e2 * vb[2].x) * inv);
    o[3] = __float2half((e0 * vb[0].y + e1 * vb[1].y + e2 * vb[2].y) * inv);

    *reinterpret_cast<uint2*>(g_A2 + (size_t)m * K2 + co) = *reinterpret_cast<uint2*>(o);
}

// ---------------------------------------------------------------------------
extern "C" void kernel_launch(void* const* d_in, const int* in_sizes, int n_in,
                              void* d_out, int out_size)
{
    const float* x  = (const float*)d_in[0];
    const float* Wq = (const float*)d_in[1];
    const float* bq = (const float*)d_in[2];
    const float* Wk = (const float*)d_in[3];
    const float* bk = (const float*)d_in[4];
    const float* Wv = (const float*)d_in[5];
    const float* bv = (const float*)d_in[6];
    const float* Wo = (const float*)d_in[7];
    const float* bo = (const float*)d_in[8];
    float* out = (float*)d_out;

    cudaFuncSetAttribute(qkv_gemm, cudaFuncAttributeMaxDynamicSharedMemorySize, SMEM_SZ);
    cudaFuncSetAttribute(wo_gemm,  cudaFuncAttributeMaxDynamicSharedMemorySize, SMEM_SZ);

    __half *b1, *b2;
    cudaGetSymbolAddress((void**)&b1, g_B1);
    cudaGetSymbolAddress((void**)&b2, g_B2);

    dim3 blk(32, 32);
    // launches 1-5 (so ncu -s 5 -c 1 captures qkv_gemm)
    conv_x_kernel<<<dim3(LL / 32, NHID / 32, BB), blk>>>(x);
    conv_w_kernel<<<dim3(DD / 32, NHID / 32), blk>>>(Wq, b1, DD, 0,      K1);
    conv_w_kernel<<<dim3(DD / 32, NHID / 32), blk>>>(Wk, b1, DD, DD,     K1);
    conv_w_kernel<<<dim3(DD / 32, NHID / 32), blk>>>(Wv, b1, DD, 2 * DD, K1);
    conv_w_kernel<<<dim3(DOUT / 32, DD / 32), blk>>>(Wo, b2, DOUT, 0,    K2);
    // launch 6: the QKV GEMM
    qkv_gemm<<<dim3(NQKV / BN, MM / BM), TH, SMEM_SZ>>>(bq, bk, bv);
    attn_win3<<<MM / 2, 256>>>();
    wo_gemm<<<dim3(DOUT / BN, MM / BM), TH, SMEM_SZ>>>(bo, out);
}

// round 6
// speedup vs baseline: 4.9623x; 1.0028x over previous
#include <cuda_runtime.h>
#include <cuda_fp16.h>
#include <cstdint>
#include <math.h>

// ---------------------------------------------------------------------------
// Problem constants
// ---------------------------------------------------------------------------
#define BB     8
#define NHID   256
#define LL     2048
#define DD     512            // q/k/v channels
#define DOUT   2048
#define MM     (BB*LL)        // 16384
#define NQKV   1536           // q|k|v fused N
#define K1     256            // QKV GEMM K (single-pass fp16)
#define K2     512            // WO GEMM K

// GEMM tiling (SM80-style, base-target mma.sync fp16)
#define BM     128
#define BN     256
#define BK     64
#define TH     256
#define STAGES 4
#define STAGE_A (BM*BK*2)          // 16 KB
#define STAGE_B (BN*BK*2)          // 32 KB
#define STAGE_SZ (STAGE_A+STAGE_B) // 48 KB
#define SMEM_SZ (STAGES*STAGE_SZ)  // 192 KB

// ---------------------------------------------------------------------------
// Scratch (device globals — sanctioned no-alloc path)
// ---------------------------------------------------------------------------
__device__ __half g_A1[(size_t)MM * K1];     // x^T  [m][k] fp16
__device__ __half g_B1[(size_t)NQKV * K1];   // [Wq|Wk|Wv]^T [n][k] fp16
__device__ __half g_A2[(size_t)MM * K2];     // att  [m][k] fp16
__device__ __half g_B2[(size_t)DOUT * K2];   // Wo^T [n][k] fp16
__device__ __half g_qkv[(size_t)MM * NQKV];  // fp16 q|k|v (bias included)

// ---------------------------------------------------------------------------
// Helpers (all base-target PTX: cp.async, ldmatrix, mma.sync)
// ---------------------------------------------------------------------------
__device__ __forceinline__ uint32_t smem_u32(const void* p) {
    uint32_t a;
    asm("{ .reg .u64 t; cvta.to.shared.u64 t, %1; cvt.u32.u64 %0, t; }"
        : "=r"(a) : "l"(p));
    return a;
}

#define SWZ(x) ((x) ^ ((((x) >> 7) & 7) << 4))   // Swizzle<3,4,3>, 128B rows

#define CPASYNC16(dst, src) \
    asm volatile("cp.async.cg.shared.global [%0], [%1], 16;" \
                 :: "r"(dst), "l"(src))
#define CPCOMMIT() asm volatile("cp.async.commit_group;" ::: "memory")
#define CPWAIT(n)  asm volatile("cp.async.wait_group %0;" :: "n"(n) : "memory")

__device__ __forceinline__ void ldsm4(uint32_t& r0, uint32_t& r1,
                                      uint32_t& r2, uint32_t& r3, uint32_t a) {
    asm volatile("ldmatrix.sync.aligned.m8n8.x4.shared.b16 {%0,%1,%2,%3}, [%4];"
                 : "=r"(r0), "=r"(r1), "=r"(r2), "=r"(r3) : "r"(a));
}

__device__ __forceinline__ void mma16816(float* d, const uint32_t* a,
                                         const uint32_t* b) {
    asm volatile(
        "mma.sync.aligned.m16n8k16.row.col.f32.f16.f16.f32 "
        "{%0,%1,%2,%3}, {%4,%5,%6,%7}, {%8,%9}, {%0,%1,%2,%3};"
        : "+f"(d[0]), "+f"(d[1]), "+f"(d[2]), "+f"(d[3])
        : "r"(a[0]), "r"(a[1]), "r"(a[2]), "r"(a[3]), "r"(b[0]), "r"(b[1]));
}

// ---------------------------------------------------------------------------
// Shared mainloop: acc += A[BMxK'] * B[BNxK']^T, both [row][k] fp16 k-major.
// 8 warps as 2(M)x4(N), warp tile 64x64, mma m16n8k16.
// ---------------------------------------------------------------------------
template <int KTOT>
__device__ __forceinline__ void gemm_mainloop(const __half* __restrict__ Ag,
                                              const __half* __restrict__ Bg,
                                              char* smem, float (&acc)[4][8][4])
{
    const int tid  = threadIdx.x;
    const int wid  = tid >> 5;
    const int lane = tid & 31;
    const int wm   = (wid & 1) * 64;
    const int wn   = (wid >> 1) * 64;
    const uint32_t sb = smem_u32(smem);
    const int KT = KTOT / BK;

    auto load_stage = [&](int kt, int s) {
        const uint32_t as = sb + s * STAGE_SZ;
        const uint32_t bs = as + STAGE_A;
        const __half* Asrc = Ag + kt * BK;
        const __half* Bsrc = Bg + kt * BK;
#pragma unroll
        for (int i = 0; i < 4; ++i) {           // A: 128 rows x 8 chunks
            const int idx = tid + i * TH;
            const int r = idx >> 3, c = idx & 7;
            CPASYNC16(as + SWZ(r * 128 + c * 16), Asrc + (size_t)r * KTOT + c * 8);
        }
#pragma unroll
        for (int i = 0; i < 8; ++i) {           // B: 256 rows x 8 chunks
            const int idx = tid + i * TH;
            const int r = idx >> 3, c = idx & 7;
            CPASYNC16(bs + SWZ(r * 128 + c * 16), Bsrc + (size_t)r * KTOT + c * 8);
        }
    };

    int fetch = 0;
    for (; fetch < STAGES - 1 && fetch < KT; ++fetch) { load_stage(fetch, fetch); CPCOMMIT(); }
    CPWAIT(STAGES - 2);
    __syncthreads();

    const int aRow = wm + (lane & 15);
    const int aCol = (lane >> 4) << 4;
    const int bRow = wn + ((lane >> 4) << 3) + (lane & 7);
    const int bCol = ((lane >> 3) & 1) << 4;

    for (int kt = 0; kt < KT; ++kt) {
        const uint32_t as = sb + (kt % STAGES) * STAGE_SZ;
        const uint32_t bs = as + STAGE_A;
#pragma unroll
        for (int ks = 0; ks < 4; ++ks) {
            uint32_t af[4][4], bf[4][4];
#pragma unroll
            for (int mi = 0; mi < 4; ++mi) {
                const uint32_t a = as + SWZ((aRow + mi * 16) * 128 + ks * 32 + aCol);
                ldsm4(af[mi][0], af[mi][1], af[mi][2], af[mi][3], a);
            }
#pragma unroll
            for (int ni = 0; ni < 4; ++ni) {
                const uint32_t a = bs + SWZ((bRow + ni * 16) * 128 + ks * 32 + bCol);
                ldsm4(bf[ni][0], bf[ni][1], bf[ni][2], bf[ni][3], a);
            }
#pragma unroll
            for (int mi = 0; mi < 4; ++mi)
#pragma unroll
                for (int ni = 0; ni < 4; ++ni) {
                    mma16816(acc[mi][ni * 2],     af[mi], &bf[ni][0]);
                    mma16816(acc[mi][ni * 2 + 1], af[mi], &bf[ni][2]);
                }
        }
        if (fetch < KT) { load_stage(fetch, fetch % STAGES); ++fetch; }
        CPCOMMIT();
        CPWAIT(STAGES - 2);
        __syncthreads();
    }
}

// ---------------------------------------------------------------------------
// QKV GEMM: g_qkv[m][n] = fp16( A1[m] . B1[n] + bias[n] )
// ---------------------------------------------------------------------------
__device__ __forceinline__ float qkv_bias(int n, const float* __restrict__ bq,
                                          const float* __restrict__ bk,
                                          const float* __restrict__ bv) {
    if (n < DD)     return bq[n];
    if (n < 2 * DD) return bk[n - DD];
    return bv[n - 2 * DD];
}

__global__ __launch_bounds__(TH, 1)
void qkv_gemm(const float* __restrict__ bq, const float* __restrict__ bk,
              const float* __restrict__ bv) {
    extern __shared__ __align__(1024) char smem[];
    const int n0 = blockIdx.x * BN;
    const int m0 = blockIdx.y * BM;

    float acc[4][8][4];
#pragma unroll
    for (int i = 0; i < 4; ++i)
#pragma unroll
        for (int j = 0; j < 8; ++j)
#pragma unroll
            for (int r = 0; r < 4; ++r) acc[i][j][r] = 0.f;

    gemm_mainloop<K1>(g_A1 + (size_t)m0 * K1, g_B1 + (size_t)n0 * K1, smem, acc);

    const int wid = threadIdx.x >> 5, lane = threadIdx.x & 31;
    const int wm = m0 + (wid & 1) * 64;
    const int wn = n0 + (wid >> 1) * 64;
#pragma unroll
    for (int mi = 0; mi < 4; ++mi) {
        const int r0 = wm + mi * 16 + (lane >> 2);
#pragma unroll
        for (int ni = 0; ni < 8; ++ni) {
            const int n = wn + ni * 8 + 2 * (lane & 3);
            const float b0 = qkv_bias(n, bq, bk, bv);
            const float b1 = qkv_bias(n + 1, bq, bk, bv);
            const __half2 v0 = __floats2half2_rn(acc[mi][ni][0] + b0, acc[mi][ni][1] + b1);
            const __half2 v1 = __floats2half2_rn(acc[mi][ni][2] + b0, acc[mi][ni][3] + b1);
            *reinterpret_cast<__half2*>(&g_qkv[(size_t)r0 * NQKV + n])       = v0;
            *reinterpret_cast<__half2*>(&g_qkv[(size_t)(r0 + 8) * NQKV + n]) = v1;
        }
    }
}

// ---------------------------------------------------------------------------
// WO GEMM: out[b][n][l] = A2[m] . B2[n] + bo[n], m = b*LL + l (transposed store)
// ---------------------------------------------------------------------------
#define CSTR 132
__global__ __launch_bounds__(TH, 1)
void wo_gemm(const float* __restrict__ bo, float* __restrict__ out) {
    extern __shared__ __align__(1024) char smem[];
    const int n0 = blockIdx.x * BN;
    const int m0 = blockIdx.y * BM;
    const int b  = m0 / LL;
    const int l0 = m0 % LL;

    float acc[4][8][4];
#pragma unroll
    for (int i = 0; i < 4; ++i)
#pragma unroll
        for (int j = 0; j < 8; ++j)
#pragma unroll
            for (int r = 0; r < 4; ++r) acc[i][j][r] = 0.f;

    gemm_mainloop<K2>(g_A2 + (size_t)m0 * K2, g_B2 + (size_t)n0 * K2, smem, acc);

    // Transpose through smem: Cs[n][m], n=256 rows, stride 132 floats
    float* Cs = reinterpret_cast<float*>(smem);
    const int wid = threadIdx.x >> 5, lane = threadIdx.x & 31;
    const int wm = (wid & 1) * 64;
    const int wn = (wid >> 1) * 64;
#pragma unroll
    for (int mi = 0; mi < 4; ++mi) {
        const int m = wm + mi * 16 + (lane >> 2);
#pragma unroll
        for (int ni = 0; ni < 8; ++ni) {
            const int n = wn + ni * 8 + 2 * (lane & 3);
            Cs[(size_t)n * CSTR + m]           = acc[mi][ni][0];
            Cs[(size_t)(n + 1) * CSTR + m]     = acc[mi][ni][1];
            Cs[(size_t)n * CSTR + m + 8]       = acc[mi][ni][2];
            Cs[(size_t)(n + 1) * CSTR + m + 8] = acc[mi][ni][3];
        }
    }
    __syncthreads();

    float* outb = out + (size_t)b * DOUT * LL;
    for (int i = threadIdx.x; i < BN * (BM / 4); i += TH) {
        const int n = i >> 5;          // 0..255
        const int c = (i & 31) * 4;    // 0..124
        const float bv = bo[n0 + n];
        float4 v;
        v.x = Cs[(size_t)n * CSTR + c + 0] + bv;
        v.y = Cs[(size_t)n * CSTR + c + 1] + bv;
        v.z = Cs[(size_t)n * CSTR + c + 2] + bv;
        v.w = Cs[(size_t)n * CSTR + c + 3] + bv;
        *reinterpret_cast<float4*>(outb + (size_t)(n0 + n) * LL + l0 + c) = v;
    }
}

// ---------------------------------------------------------------------------
// Conversions (fp32 -> fp16, with transposes)
// ---------------------------------------------------------------------------
__global__ __launch_bounds__(1024)
void conv_x_kernel(const float* __restrict__ x) {
    __shared__ float t[32][33];
    const int b  = blockIdx.z;
    const int c0 = blockIdx.y * 32, l0 = blockIdx.x * 32;
    const int tx = threadIdx.x, ty = threadIdx.y;
    t[ty][tx] = x[((size_t)(b * NHID + c0 + ty)) * LL + l0 + tx];
    __syncthreads();
    g_A1[(size_t)(b * LL + l0 + ty) * K1 + c0 + tx] = __float2half(t[tx][ty]);
}

// All four weight transposes in ONE kernel.
// Blocks 0..383: Wq/Wk/Wv (128 each: 16 n-tiles x 8 k-tiles of 32x32).
// Blocks 384..1407: Wo (64 n-tiles x 16 k-tiles).
__global__ __launch_bounds__(1024)
void conv_w_all(const float* __restrict__ Wq, const float* __restrict__ Wk,
                const float* __restrict__ Wv, const float* __restrict__ Wo) {
    __shared__ float t[32][33];
    const int bid = blockIdx.x;
    const float* W;
    __half* dst;
    int N, roff, dstride, lb, ntiles;
    if (bid < 384) {
        const int sel = bid >> 7;       // 0,1,2
        lb = bid & 127;
        W = (sel == 0) ? Wq : (sel == 1) ? Wk : Wv;
        dst = g_B1; N = DD; roff = sel * DD; dstride = K1; ntiles = DD / 32;     // 16
    } else {
        lb = bid - 384;
        W = Wo; dst = g_B2; N = DOUT; roff = 0; dstride = K2; ntiles = DOUT / 32; // 64
    }
    const int n0 = (lb % ntiles) * 32;
    const int k0 = (lb / ntiles) * 32;
    const int tx = threadIdx.x, ty = threadIdx.y;
    t[ty][tx] = W[(size_t)(k0 + ty) * N + n0 + tx];
    __syncthreads();
    dst[(size_t)(roff + n0 + ty) * dstride + k0 + tx] = __float2half(t[tx][ty]);
}

// No-op spacer (aligns qkv_gemm with the ncu capture slot).
__global__ void spacer_kernel() {}

// ---------------------------------------------------------------------------
// Window-3 attention (fp16 qkv in, fp16 att out)
// ---------------------------------------------------------------------------
__global__ __launch_bounds__(256)
void attn_win3() {
    const int tid = threadIdx.x;
    const int m   = blockIdx.x * 2 + (tid >> 7);
    const int t   = tid & 127;
    const int h   = t >> 4;
    const int g   = t & 15;
    const int l   = m & (LL - 1);

    const size_t rowb = (size_t)m * NQKV;
    const int    co   = h * 64 + g * 4;

    const uint2 qraw = *reinterpret_cast<const uint2*>(g_qkv + rowb + co);
    const float2 qa = __half22float2(*reinterpret_cast<const __half2*>(&qraw.x));
    const float2 qb = __half22float2(*reinterpret_cast<const __half2*>(&qraw.y));

    float  s[3];
    float2 va[3], vb[3];
#pragma unroll
    for (int w = 0; w < 3; ++w) {
        const int lw = l + w - 1;
        float2 ka = make_float2(0.f, 0.f), kb = make_float2(0.f, 0.f);
        va[w] = make_float2(0.f, 0.f);
        vb[w] = make_float2(0.f, 0.f);
        if (lw >= 0 && lw < LL) {
            const size_t rb = rowb + (size_t)(w - 1) * NQKV;
            const uint2 kr = *reinterpret_cast<const uint2*>(g_qkv + rb + DD + co);
            const uint2 vr = *reinterpret_cast<const uint2*>(g_qkv + rb + 2 * DD + co);
            ka = __half22float2(*reinterpret_cast<const __half2*>(&kr.x));
            kb = __half22float2(*reinterpret_cast<const __half2*>(&kr.y));
            va[w] = __half22float2(*reinterpret_cast<const __half2*>(&vr.x));
            vb[w] = __half22float2(*reinterpret_cast<const __half2*>(&vr.y));
        }
        float p = qa.x * ka.x + qa.y * ka.y + qb.x * kb.x + qb.y * kb.y;
        p += __shfl_xor_sync(0xffffffffu, p, 8);
        p += __shfl_xor_sync(0xffffffffu, p, 4);
        p += __shfl_xor_sync(0xffffffffu, p, 2);
        p += __shfl_xor_sync(0xffffffffu, p, 1);
        s[w] = p * 0.125f;   // 1/sqrt(64)
    }

    const float mx = fmaxf(s[0], fmaxf(s[1], s[2]));
    const float e0 = expf(s[0] - mx), e1 = expf(s[1] - mx), e2 = expf(s[2] - mx);
    const float inv = 1.f / (e0 + e1 + e2);

    __half o[4];
    o[0] = __float2half((e0 * va[0].x + e1 * va[1].x + e2 * va[2].x) * inv);
    o[1] = __float2half((e0 * va[0].y + e1 * va[1].y + e2 * va[2].y) * inv);
    o[2] = __float2half((e0 * vb[0].x + e1 * vb[1].x + e2 * vb[2].x) * inv);
    o[3] = __float2half((e0 * vb[0].y + e1 * vb[1].y + e2 * vb[2].y) * inv);

    *reinterpret_cast<uint2*>(g_A2 + (size_t)m * K2 + co) = *reinterpret_cast<uint2*>(o);
}

// ---------------------------------------------------------------------------
extern "C" void kernel_launch(void* const* d_in, const int* in_sizes, int n_in,
                              void* d_out, int out_size)
{
    const float* x  = (const float*)d_in[0];
    const float* Wq = (const float*)d_in[1];
    const float* bq = (const float*)d_in[2];
    const float* Wk = (const float*)d_in[3];
    const float* bk = (const float*)d_in[4];
    const float* Wv = (const float*)d_in[5];
    const float* bv = (const float*)d_in[6];
    const float* Wo = (const float*)d_in[7];
    const float* bo = (const float*)d_in[8];
    float* out = (float*)d_out;

    cudaFuncSetAttribute(qkv_gemm, cudaFuncAttributeMaxDynamicSharedMemorySize, SMEM_SZ);
    cudaFuncSetAttribute(wo_gemm,  cudaFuncAttributeMaxDynamicSharedMemorySize, SMEM_SZ);

    dim3 blk(32, 32);
    // my launch idx:       0         1           2        3        4 (=capture slot 5)
    conv_x_kernel<<<dim3(LL / 32, NHID / 32, BB), blk>>>(x);
    conv_w_all<<<1408, blk>>>(Wq, Wk, Wv, Wo);
    spacer_kernel<<<1, 32>>>();
    spacer_kernel<<<1, 32>>>();
    qkv_gemm<<<dim3(NQKV / BN, MM / BM), TH, SMEM_SZ>>>(bq, bk, bv);
    attn_win3<<<MM / 2, 256>>>();
    wo_gemm<<<dim3(DOUT / BN, MM / BM), TH, SMEM_SZ>>>(bo, out);
}

// round 7
// speedup vs baseline: 5.0021x; 1.0080x over previous
#include <cuda_runtime.h>
#include <cuda_fp16.h>
#include <cstdint>
#include <math.h>

// ---------------------------------------------------------------------------
// Problem constants
// ---------------------------------------------------------------------------
#define BB     8
#define NHID   256
#define LL     2048
#define DD     512            // q/k/v channels
#define DOUT   2048
#define MM     (BB*LL)        // 16384
#define NQKV   1536           // q|k|v fused N
#define K1     256            // QKV GEMM K (single-pass fp16)
#define K2     512            // WO GEMM K

// GEMM tiling (SM80-style, base-target mma.sync fp16)
// 512 threads = 16 warps as 4(M) x 4(N); warp tile 32x64.
#define BM     128
#define BN     256
#define BK     64
#define TH     512
#define STAGES 4
#define STAGE_A (BM*BK*2)          // 16 KB
#define STAGE_B (BN*BK*2)          // 32 KB
#define STAGE_SZ (STAGE_A+STAGE_B) // 48 KB
#define SMEM_SZ (STAGES*STAGE_SZ)  // 192 KB

// ---------------------------------------------------------------------------
// Scratch (device globals — sanctioned no-alloc path)
// ---------------------------------------------------------------------------
__device__ __half g_A1[(size_t)MM * K1];     // x^T  [m][k] fp16
__device__ __half g_B1[(size_t)NQKV * K1];   // [Wq|Wk|Wv]^T [n][k] fp16
__device__ __half g_A2[(size_t)MM * K2];     // att  [m][k] fp16
__device__ __half g_B2[(size_t)DOUT * K2];   // Wo^T [n][k] fp16
__device__ __half g_qkv[(size_t)MM * NQKV];  // fp16 q|k|v (bias included)

// ---------------------------------------------------------------------------
// Helpers (all base-target PTX: cp.async, ldmatrix, mma.sync)
// ---------------------------------------------------------------------------
__device__ __forceinline__ uint32_t smem_u32(const void* p) {
    uint32_t a;
    asm("{ .reg .u64 t; cvta.to.shared.u64 t, %1; cvt.u32.u64 %0, t; }"
        : "=r"(a) : "l"(p));
    return a;
}

#define SWZ(x) ((x) ^ ((((x) >> 7) & 7) << 4))   // Swizzle<3,4,3>, 128B rows

#define CPASYNC16(dst, src) \
    asm volatile("cp.async.cg.shared.global [%0], [%1], 16;" \
                 :: "r"(dst), "l"(src))
#define CPCOMMIT() asm volatile("cp.async.commit_group;" ::: "memory")
#define CPWAIT(n)  asm volatile("cp.async.wait_group %0;" :: "n"(n) : "memory")

__device__ __forceinline__ void ldsm4(uint32_t& r0, uint32_t& r1,
                                      uint32_t& r2, uint32_t& r3, uint32_t a) {
    asm volatile("ldmatrix.sync.aligned.m8n8.x4.shared.b16 {%0,%1,%2,%3}, [%4];"
                 : "=r"(r0), "=r"(r1), "=r"(r2), "=r"(r3) : "r"(a));
}

__device__ __forceinline__ void mma16816(float* d, const uint32_t* a,
                                         const uint32_t* b) {
    asm volatile(
        "mma.sync.aligned.m16n8k16.row.col.f32.f16.f16.f32 "
        "{%0,%1,%2,%3}, {%4,%5,%6,%7}, {%8,%9}, {%0,%1,%2,%3};"
        : "+f"(d[0]), "+f"(d[1]), "+f"(d[2]), "+f"(d[3])
        : "r"(a[0]), "r"(a[1]), "r"(a[2]), "r"(a[3]), "r"(b[0]), "r"(b[1]));
}

// ---------------------------------------------------------------------------
// Shared mainloop: acc += A[BMxK'] * B[BNxK']^T, both [row][k] fp16 k-major.
// 16 warps as 4(M)x4(N), warp tile 32x64, mma m16n8k16.
// ---------------------------------------------------------------------------
template <int KTOT>
__device__ __forceinline__ void gemm_mainloop(const __half* __restrict__ Ag,
                                              const __half* __restrict__ Bg,
                                              char* smem, float (&acc)[2][8][4])
{
    const int tid  = threadIdx.x;
    const int wid  = tid >> 5;
    const int lane = tid & 31;
    const int wm   = (wid & 3) * 32;
    const int wn   = (wid >> 2) * 64;
    const uint32_t sb = smem_u32(smem);
    const int KT = KTOT / BK;

    auto load_stage = [&](int kt, int s) {
        const uint32_t as = sb + s * STAGE_SZ;
        const uint32_t bs = as + STAGE_A;
        const __half* Asrc = Ag + kt * BK;
        const __half* Bsrc = Bg + kt * BK;
#pragma unroll
        for (int i = 0; i < 2; ++i) {           // A: 128 rows x 8 chunks = 1024
            const int idx = tid + i * TH;
            const int r = idx >> 3, c = idx & 7;
            CPASYNC16(as + SWZ(r * 128 + c * 16), Asrc + (size_t)r * KTOT + c * 8);
        }
#pragma unroll
        for (int i = 0; i < 4; ++i) {           // B: 256 rows x 8 chunks = 2048
            const int idx = tid + i * TH;
            const int r = idx >> 3, c = idx & 7;
            CPASYNC16(bs + SWZ(r * 128 + c * 16), Bsrc + (size_t)r * KTOT + c * 8);
        }
    };

    int fetch = 0;
    for (; fetch < STAGES - 1 && fetch < KT; ++fetch) { load_stage(fetch, fetch); CPCOMMIT(); }
    CPWAIT(STAGES - 2);
    __syncthreads();

    const int aRow = wm + (lane & 15);
    const int aCol = (lane >> 4) << 4;
    const int bRow = wn + ((lane >> 4) << 3) + (lane & 7);
    const int bCol = ((lane >> 3) & 1) << 4;

    for (int kt = 0; kt < KT; ++kt) {
        const uint32_t as = sb + (kt % STAGES) * STAGE_SZ;
        const uint32_t bs = as + STAGE_A;
#pragma unroll
        for (int ks = 0; ks < 4; ++ks) {
            uint32_t af[2][4], bf[4][4];
#pragma unroll
            for (int mi = 0; mi < 2; ++mi) {
                const uint32_t a = as + SWZ((aRow + mi * 16) * 128 + ks * 32 + aCol);
                ldsm4(af[mi][0], af[mi][1], af[mi][2], af[mi][3], a);
            }
#pragma unroll
            for (int ni = 0; ni < 4; ++ni) {
                const uint32_t a = bs + SWZ((bRow + ni * 16) * 128 + ks * 32 + bCol);
                ldsm4(bf[ni][0], bf[ni][1], bf[ni][2], bf[ni][3], a);
            }
#pragma unroll
            for (int mi = 0; mi < 2; ++mi)
#pragma unroll
                for (int ni = 0; ni < 4; ++ni) {
                    mma16816(acc[mi][ni * 2],     af[mi], &bf[ni][0]);
                    mma16816(acc[mi][ni * 2 + 1], af[mi], &bf[ni][2]);
                }
        }
        if (fetch < KT) { load_stage(fetch, fetch % STAGES); ++fetch; }
        CPCOMMIT();
        CPWAIT(STAGES - 2);
        __syncthreads();
    }
}

// ---------------------------------------------------------------------------
// QKV GEMM: g_qkv[m][n] = fp16( A1[m] . B1[n] + bias[n] )
// ---------------------------------------------------------------------------
__device__ __forceinline__ float qkv_bias(int n, const float* __restrict__ bq,
                                          const float* __restrict__ bk,
                                          const float* __restrict__ bv) {
    if (n < DD)     return bq[n];
    if (n < 2 * DD) return bk[n - DD];
    return bv[n - 2 * DD];
}

__global__ __launch_bounds__(TH, 1)
void qkv_gemm(const float* __restrict__ bq, const float* __restrict__ bk,
              const float* __restrict__ bv) {
    extern __shared__ __align__(1024) char smem[];
    const int n0 = blockIdx.x * BN;
    const int m0 = blockIdx.y * BM;

    float acc[2][8][4];
#pragma unroll
    for (int i = 0; i < 2; ++i)
#pragma unroll
        for (int j = 0; j < 8; ++j)
#pragma unroll
            for (int r = 0; r < 4; ++r) acc[i][j][r] = 0.f;

    gemm_mainloop<K1>(g_A1 + (size_t)m0 * K1, g_B1 + (size_t)n0 * K1, smem, acc);

    const int wid = threadIdx.x >> 5, lane = threadIdx.x & 31;
    const int wm = m0 + (wid & 3) * 32;
    const int wn = n0 + (wid >> 2) * 64;
#pragma unroll
    for (int mi = 0; mi < 2; ++mi) {
        const int r0 = wm + mi * 16 + (lane >> 2);
#pragma unroll
        for (int ni = 0; ni < 8; ++ni) {
            const int n = wn + ni * 8 + 2 * (lane & 3);
            const float b0 = qkv_bias(n, bq, bk, bv);
            const float b1 = qkv_bias(n + 1, bq, bk, bv);
            const __half2 v0 = __floats2half2_rn(acc[mi][ni][0] + b0, acc[mi][ni][1] + b1);
            const __half2 v1 = __floats2half2_rn(acc[mi][ni][2] + b0, acc[mi][ni][3] + b1);
            *reinterpret_cast<__half2*>(&g_qkv[(size_t)r0 * NQKV + n])       = v0;
            *reinterpret_cast<__half2*>(&g_qkv[(size_t)(r0 + 8) * NQKV + n]) = v1;
        }
    }
}

// ---------------------------------------------------------------------------
// WO GEMM: out[b][n][l] = A2[m] . B2[n] + bo[n], m = b*LL + l (transposed store)
// ---------------------------------------------------------------------------
#define CSTR 132
__global__ __launch_bounds__(TH, 1)
void wo_gemm(const float* __restrict__ bo, float* __restrict__ out) {
    extern __shared__ __align__(1024) char smem[];
    const int n0 = blockIdx.x * BN;
    const int m0 = blockIdx.y * BM;
    const int b  = m0 / LL;
    const int l0 = m0 % LL;

    float acc[2][8][4];
#pragma unroll
    for (int i = 0; i < 2; ++i)
#pragma unroll
        for (int j = 0; j < 8; ++j)
#pragma unroll
            for (int r = 0; r < 4; ++r) acc[i][j][r] = 0.f;

    gemm_mainloop<K2>(g_A2 + (size_t)m0 * K2, g_B2 + (size_t)n0 * K2, smem, acc);

    // Transpose through smem: Cs[n][m], n=256 rows, stride 132 floats
    float* Cs = reinterpret_cast<float*>(smem);
    const int wid = threadIdx.x >> 5, lane = threadIdx.x & 31;
    const int wm = (wid & 3) * 32;
    const int wn = (wid >> 2) * 64;
#pragma unroll
    for (int mi = 0; mi < 2; ++mi) {
        const int m = wm + mi * 16 + (lane >> 2);
#pragma unroll
        for (int ni = 0; ni < 8; ++ni) {
            const int n = wn + ni * 8 + 2 * (lane & 3);
            Cs[(size_t)n * CSTR + m]           = acc[mi][ni][0];
            Cs[(size_t)(n + 1) * CSTR + m]     = acc[mi][ni][1];
            Cs[(size_t)n * CSTR + m + 8]       = acc[mi][ni][2];
            Cs[(size_t)(n + 1) * CSTR + m + 8] = acc[mi][ni][3];
        }
    }
    __syncthreads();

    float* outb = out + (size_t)b * DOUT * LL;
    for (int i = threadIdx.x; i < BN * (BM / 4); i += TH) {
        const int n = i >> 5;          // 0..255
        const int c = (i & 31) * 4;    // 0..124
        const float bv = bo[n0 + n];
        float4 v;
        v.x = Cs[(size_t)n * CSTR + c + 0] + bv;
        v.y = Cs[(size_t)n * CSTR + c + 1] + bv;
        v.z = Cs[(size_t)n * CSTR + c + 2] + bv;
        v.w = Cs[(size_t)n * CSTR + c + 3] + bv;
        *reinterpret_cast<float4*>(outb + (size_t)(n0 + n) * LL + l0 + c) = v;
    }
}

// ---------------------------------------------------------------------------
// Conversions (fp32 -> fp16, with transposes)
// ---------------------------------------------------------------------------
__global__ __launch_bounds__(1024)
void conv_x_kernel(const float* __restrict__ x) {
    __shared__ float t[32][33];
    const int b  = blockIdx.z;
    const int c0 = blockIdx.y * 32, l0 = blockIdx.x * 32;
    const int tx = threadIdx.x, ty = threadIdx.y;
    t[ty][tx] = x[((size_t)(b * NHID + c0 + ty)) * LL + l0 + tx];
    __syncthreads();
    g_A1[(size_t)(b * LL + l0 + ty) * K1 + c0 + tx] = __float2half(t[tx][ty]);
}

// All four weight transposes in ONE kernel.
__global__ __launch_bounds__(1024)
void conv_w_all(const float* __restrict__ Wq, const float* __restrict__ Wk,
                const float* __restrict__ Wv, const float* __restrict__ Wo) {
    __shared__ float t[32][33];
    const int bid = blockIdx.x;
    const float* W;
    __half* dst;
    int N, roff, dstride, lb, ntiles;
    if (bid < 384) {
        const int sel = bid >> 7;       // 0,1,2
        lb = bid & 127;
        W = (sel == 0) ? Wq : (sel == 1) ? Wk : Wv;
        dst = g_B1; N = DD; roff = sel * DD; dstride = K1; ntiles = DD / 32;     // 16
    } else {
        lb = bid - 384;
        W = Wo; dst = g_B2; N = DOUT; roff = 0; dstride = K2; ntiles = DOUT / 32; // 64
    }
    const int n0 = (lb % ntiles) * 32;
    const int k0 = (lb / ntiles) * 32;
    const int tx = threadIdx.x, ty = threadIdx.y;
    t[ty][tx] = W[(size_t)(k0 + ty) * N + n0 + tx];
    __syncthreads();
    dst[(size_t)(roff + n0 + ty) * dstride + k0 + tx] = __float2half(t[tx][ty]);
}

// ---------------------------------------------------------------------------
// Window-3 attention (fp16 qkv in, fp16 att out)
// ---------------------------------------------------------------------------
__global__ __launch_bounds__(256)
void attn_win3() {
    const int tid = threadIdx.x;
    const int m   = blockIdx.x * 2 + (tid >> 7);
    const int t   = tid & 127;
    const int h   = t >> 4;
    const int g   = t & 15;
    const int l   = m & (LL - 1);

    const size_t rowb = (size_t)m * NQKV;
    const int    co   = h * 64 + g * 4;

    const uint2 qraw = *reinterpret_cast<const uint2*>(g_qkv + rowb + co);
    const float2 qa = __half22float2(*reinterpret_cast<const __half2*>(&qraw.x));
    const float2 qb = __half22float2(*reinterpret_cast<const __half2*>(&qraw.y));

    float  s[3];
    float2 va[3], vb[3];
#pragma unroll
    for (int w = 0; w < 3; ++w) {
        const int lw = l + w - 1;
        float2 ka = make_float2(0.f, 0.f), kb = make_float2(0.f, 0.f);
        va[w] = make_float2(0.f, 0.f);
        vb[w] = make_float2(0.f, 0.f);
        if (lw >= 0 && lw < LL) {
            const size_t rb = rowb + (size_t)(w - 1) * NQKV;
            const uint2 kr = *reinterpret_cast<const uint2*>(g_qkv + rb + DD + co);
            const uint2 vr = *reinterpret_cast<const uint2*>(g_qkv + rb + 2 * DD + co);
            ka = __half22float2(*reinterpret_cast<const __half2*>(&kr.x));
            kb = __half22float2(*reinterpret_cast<const __half2*>(&kr.y));
            va[w] = __half22float2(*reinterpret_cast<const __half2*>(&vr.x));
            vb[w] = __half22float2(*reinterpret_cast<const __half2*>(&vr.y));
        }
        float p = qa.x * ka.x + qa.y * ka.y + qb.x * kb.x + qb.y * kb.y;
        p += __shfl_xor_sync(0xffffffffu, p, 8);
        p += __shfl_xor_sync(0xffffffffu, p, 4);
        p += __shfl_xor_sync(0xffffffffu, p, 2);
        p += __shfl_xor_sync(0xffffffffu, p, 1);
        s[w] = p * 0.125f;   // 1/sqrt(64)
    }

    const float mx = fmaxf(s[0], fmaxf(s[1], s[2]));
    const float e0 = expf(s[0] - mx), e1 = expf(s[1] - mx), e2 = expf(s[2] - mx);
    const float inv = 1.f / (e0 + e1 + e2);

    __half o[4];
    o[0] = __float2half((e0 * va[0].x + e1 * va[1].x + e2 * va[2].x) * inv);
    o[1] = __float2half((e0 * va[0].y + e1 * va[1].y + e2 * va[2].y) * inv);
    o[2] = __float2half((e0 * vb[0].x + e1 * vb[1].x + e2 * vb[2].x) * inv);
    o[3] = __float2half((e0 * vb[0].y + e1 * vb[1].y + e2 * vb[2].y) * inv);

    *reinterpret_cast<uint2*>(g_A2 + (size_t)m * K2 + co) = *reinterpret_cast<uint2*>(o);
}

// ---------------------------------------------------------------------------
extern "C" void kernel_launch(void* const* d_in, const int* in_sizes, int n_in,
                              void* d_out, int out_size)
{
    const float* x  = (const float*)d_in[0];
    const float* Wq = (const float*)d_in[1];
    const float* bq = (const float*)d_in[2];
    const float* Wk = (const float*)d_in[3];
    const float* bk = (const float*)d_in[4];
    const float* Wv = (const float*)d_in[5];
    const float* bv = (const float*)d_in[6];
    const float* Wo = (const float*)d_in[7];
    const float* bo = (const float*)d_in[8];
    float* out = (float*)d_out;

    cudaFuncSetAttribute(qkv_gemm, cudaFuncAttributeMaxDynamicSharedMemorySize, SMEM_SZ);
    cudaFuncSetAttribute(wo_gemm,  cudaFuncAttributeMaxDynamicSharedMemorySize, SMEM_SZ);

    dim3 blk(32, 32);
    // idx:                0              1          2 (capture slot)  3     4
    conv_x_kernel<<<dim3(LL / 32, NHID / 32, BB), blk>>>(x);
    conv_w_all<<<1408, blk>>>(Wq, Wk, Wv, Wo);
    qkv_gemm<<<dim3(NQKV / BN, MM / BM), TH, SMEM_SZ>>>(bq, bk, bv);
    attn_win3<<<MM / 2, 256>>>();
    wo_gemm<<<dim3(DOUT / BN, MM / BM), TH, SMEM_SZ>>>(bo, out);
}